// round 12
// baseline (speedup 1.0000x reference)
#include <cuda_runtime.h>
#include <cuda_bf16.h>
#include <math.h>
#include <cstdint>

#define BATCH 4
#define CDIM  256
#define NSP   4096
#define BN2   16777216
#define KTOT  768          // [hi | lo | hi] x [hi | hi | lo]
#define NCHUNK 12          // K chunks of 64

// ---------------------------------------------------------------------------
// Device scratch
// ---------------------------------------------------------------------------
__device__ float g_rowsum[BATCH * NSP];
__device__ float g_colsum[BATCH * NSP];
__device__ float g_invr[BATCH * NSP];
__device__ float g_invc[BATCH * NSP];
__device__ __nv_bfloat16 g_P[(size_t)BATCH * NSP * KTOT];
__device__ __nv_bfloat16 g_Q[(size_t)BATCH * NSP * KTOT];
__device__ float g_E[(size_t)BATCH * BN2];       // e = exp(alpha*dot)
__device__ float g_cpart[BATCH * 4 * 3 * NSP];   // [b][rowquarter][3][col]

// ---------------------------------------------------------------------------
// PTX helpers (sm_80-compatible: cp.async, ldmatrix, mma.sync)
// ---------------------------------------------------------------------------
__device__ __forceinline__ uint32_t smem_u32(const void* p) {
    uint32_t a;
    asm("{ .reg .u64 t; cvta.to.shared.u64 t, %1; cvt.u32.u64 %0, t; }"
        : "=r"(a) : "l"(p));
    return a;
}
__device__ __forceinline__ void cp16(uint32_t s, const void* g) {
    asm volatile("cp.async.cg.shared.global [%0], [%1], 16;" :: "r"(s), "l"(g));
}
__device__ __forceinline__ void cp_commit() {
    asm volatile("cp.async.commit_group;");
}
template <int N>
__device__ __forceinline__ void cp_wait() {
    asm volatile("cp.async.wait_group %0;" :: "n"(N));
}
__device__ __forceinline__ void ldmx4(uint32_t* r, uint32_t addr) {
    asm volatile("ldmatrix.sync.aligned.m8n8.x4.shared.b16 {%0,%1,%2,%3}, [%4];"
                 : "=r"(r[0]), "=r"(r[1]), "=r"(r[2]), "=r"(r[3]) : "r"(addr));
}
__device__ __forceinline__ void mma16816(float* d, const uint32_t* a, const uint32_t* b) {
    asm volatile(
        "mma.sync.aligned.m16n8k16.row.col.f32.bf16.bf16.f32 "
        "{%0,%1,%2,%3}, {%4,%5,%6,%7}, {%8,%9}, {%0,%1,%2,%3};"
        : "+f"(d[0]), "+f"(d[1]), "+f"(d[2]), "+f"(d[3])
        : "r"(a[0]), "r"(a[1]), "r"(a[2]), "r"(a[3]), "r"(b[0]), "r"(b[1]));
}

// ---------------------------------------------------------------------------
// Kernel 1: prep — L2-normalize over channels, bf16 hi/lo split, K-major
// [m][768]. Also zeroes the sum accumulators.
// ---------------------------------------------------------------------------
__global__ __launch_bounds__(256)
void prep_kernel(const float* __restrict__ xp, const float* __restrict__ xq) {
    __shared__ float tile[32][257];
    const int m0 = blockIdx.x * 32;
    const int b  = blockIdx.y;
    const int t  = threadIdx.x;
    const int w  = t >> 5, lane = t & 31;
    const bool isP = (blockIdx.z == 0);
    const float* src = isP ? xp : xq;
    __nv_bfloat16* dst = isP ? g_P : g_Q;

    if (blockIdx.z == 0 && blockIdx.y == 0 && blockIdx.x < 64) {
        int idx = blockIdx.x * 256 + t;
        g_rowsum[idx] = 0.0f;
        g_colsum[idx] = 0.0f;
    }

    #pragma unroll 8
    for (int it = 0; it < 32; it++) {
        int c = w + it * 8;
        tile[lane][c] = src[((size_t)b * CDIM + c) * NSP + m0 + lane];
    }
    __syncthreads();

    #pragma unroll
    for (int r = 0; r < 4; r++) {
        int row = w * 4 + r;
        float s = 0.0f;
        #pragma unroll
        for (int k = 0; k < 8; k++) {
            float v = tile[row][lane + 32 * k];
            s = fmaf(v, v, s);
        }
        #pragma unroll
        for (int off = 16; off > 0; off >>= 1)
            s += __shfl_down_sync(0xFFFFFFFFu, s, off);
        float invn = 1.0f / fmaxf(sqrtf(__shfl_sync(0xFFFFFFFFu, s, 0)), 1e-12f);

        size_t obase = ((size_t)b * NSP + m0 + row) * KTOT;
        #pragma unroll
        for (int k = 0; k < 8; k++) {
            int c = lane + 32 * k;
            float v = tile[row][c] * invn;
            __nv_bfloat16 hi = __float2bfloat16(v);
            __nv_bfloat16 lo = __float2bfloat16(v - __bfloat162float(hi));
            dst[obase + c] = hi;
            dst[obase + 256 + c] = isP ? lo : hi;
            dst[obase + 512 + c] = isP ? hi : lo;
        }
    }
}

// ---------------------------------------------------------------------------
// Kernel 2: HMMA GEMM (128x128, K=768, 2 CTA/SM, double buffer) [R10 config]
// + exp epilogue with smem-staged 128B-coalesced stores to g_E.
// ---------------------------------------------------------------------------
#define SMEM_BUFS  1024
#define SMEM_TOTAL (1024 + 4 * 16384)

__global__ __launch_bounds__(256, 2)
void gemm_exp_kernel(const float* __restrict__ alpha_p) {
    extern __shared__ char smem[];
    const uint32_t sbase = smem_u32(smem);
    float* srow = (float*)smem;
    float* scol = (float*)(smem + 512);

    const int t = threadIdx.x;
    const int w = t >> 5, lane = t & 31;
    const int b  = blockIdx.z;
    const int i0 = blockIdx.y * 128;
    const int j0 = blockIdx.x * 128;

    if (t < 128) { srow[t] = 0.0f; scol[t] = 0.0f; }

    const __nv_bfloat16* Abase = g_P + ((size_t)b * NSP + i0) * KTOT;
    const __nv_bfloat16* Bbase = g_Q + ((size_t)b * NSP + j0) * KTOT;

    auto load_chunk = [&](int c, int buf) {
        uint32_t aS = sbase + SMEM_BUFS + buf * 32768;
        uint32_t bS = aS + 16384;
        #pragma unroll
        for (int u = 0; u < 4; u++) {
            int f = t + 256 * u;
            uint32_t row = f >> 3, seg = f & 7;
            uint32_t off = row * 128 + ((seg ^ (row & 7)) << 4);
            cp16(aS + off, Abase + (size_t)row * KTOT + c * 64 + seg * 8);
            cp16(bS + off, Bbase + (size_t)row * KTOT + c * 64 + seg * 8);
        }
    };

    const int wm = w >> 2, wn = w & 3;
    const int r16 = lane & 15, ahi = lane >> 4;
    const int bn  = (lane & 7) + ((lane >> 4) << 3);
    const int bkl = (lane >> 3) & 1;

    float d[4][4][4] = {};

    load_chunk(0, 0);
    cp_commit();

    #pragma unroll 1
    for (int c = 0; c < NCHUNK; c++) {
        if (c < NCHUNK - 1) { load_chunk(c + 1, (c + 1) & 1); cp_commit(); }
        if (c < NCHUNK - 1) cp_wait<1>(); else cp_wait<0>();
        __syncthreads();

        uint32_t aS = sbase + SMEM_BUFS + (c & 1) * 32768;
        uint32_t bS = aS + 16384;

        #pragma unroll
        for (int kk = 0; kk < 4; kk++) {
            uint32_t afr[4][4];
            #pragma unroll
            for (int mt = 0; mt < 4; mt++) {
                uint32_t row = wm * 64 + mt * 16 + r16;
                uint32_t col = (((2 * kk + ahi) ^ (r16 & 7)) << 4);
                ldmx4(afr[mt], aS + row * 128 + col);
            }
            uint32_t bfr[4][2];
            #pragma unroll
            for (int np = 0; np < 2; np++) {
                uint32_t nrow = wn * 32 + np * 16 + bn;
                uint32_t col = (((2 * kk + bkl) ^ (bn & 7)) << 4);
                uint32_t q[4];
                ldmx4(q, bS + nrow * 128 + col);
                bfr[2 * np][0] = q[0]; bfr[2 * np][1] = q[1];
                bfr[2 * np + 1][0] = q[2]; bfr[2 * np + 1][1] = q[3];
            }
            #pragma unroll
            for (int mt = 0; mt < 4; mt++)
                #pragma unroll
                for (int nt = 0; nt < 4; nt++)
                    mma16816(d[mt][nt], afr[mt], bfr[nt]);
        }
        __syncthreads();
    }

    // ---- epilogue: e = exp(alpha*dot); row/col sums; staged coalesced store
    const float alpha = __ldg(alpha_p);
    const int g = lane >> 2, tg = lane & 3;
    float csum[4][2] = {};

    #pragma unroll
    for (int mt = 0; mt < 4; mt++) {
        float rs0 = 0.0f, rs1 = 0.0f;
        #pragma unroll
        for (int nt = 0; nt < 4; nt++) {
            float e0 = __expf(d[mt][nt][0] * alpha);
            float e1 = __expf(d[mt][nt][1] * alpha);
            float e2 = __expf(d[mt][nt][2] * alpha);
            float e3 = __expf(d[mt][nt][3] * alpha);
            d[mt][nt][0] = e0; d[mt][nt][1] = e1;
            d[mt][nt][2] = e2; d[mt][nt][3] = e3;
            rs0 += e0 + e1; rs1 += e2 + e3;
            csum[nt][0] += e0 + e2; csum[nt][1] += e1 + e3;
        }
        rs0 += __shfl_xor_sync(0xFFFFFFFFu, rs0, 1);
        rs0 += __shfl_xor_sync(0xFFFFFFFFu, rs0, 2);
        rs1 += __shfl_xor_sync(0xFFFFFFFFu, rs1, 1);
        rs1 += __shfl_xor_sync(0xFFFFFFFFu, rs1, 2);
        if (tg == 0) {
            atomicAdd(&srow[wm * 64 + mt * 16 + g],     rs0);
            atomicAdd(&srow[wm * 64 + mt * 16 + g + 8], rs1);
        }
    }
    #pragma unroll
    for (int nt = 0; nt < 4; nt++)
        #pragma unroll
        for (int cc = 0; cc < 2; cc++) {
            float v = csum[nt][cc];
            v += __shfl_xor_sync(0xFFFFFFFFu, v, 4);
            v += __shfl_xor_sync(0xFFFFFFFFu, v, 8);
            v += __shfl_xor_sync(0xFFFFFFFFu, v, 16);
            if (g == 0) atomicAdd(&scol[wn * 32 + nt * 8 + tg * 2 + cc], v);
        }

    // staged coalesced stores: 4 groups of 32 rows, stage [col][row] stride 33
    float* stage = (float*)(smem + SMEM_BUFS);   // 16.9 KB in dead pipeline smem
    float* outb = g_E + (size_t)b * BN2;
    const int sc = t & 127, srh = t >> 7;
    #pragma unroll 1
    for (int rg = 0; rg < 4; rg++) {
        __syncthreads();                 // stage free / prev group consumed
        if (wm == (rg >> 1)) {
            #pragma unroll
            for (int p = 0; p < 2; p++) {
                const int mt = (rg & 1) * 2 + p;
                const int rb = p * 16 + g;
                #pragma unroll
                for (int nt = 0; nt < 4; nt++) {
                    const int c = wn * 32 + nt * 8 + tg * 2;
                    stage[c * 33 + rb]           = d[mt][nt][0];
                    stage[(c + 1) * 33 + rb]     = d[mt][nt][1];
                    stage[c * 33 + rb + 8]       = d[mt][nt][2];
                    stage[(c + 1) * 33 + rb + 8] = d[mt][nt][3];
                }
            }
        }
        __syncthreads();
        #pragma unroll
        for (int u = 0; u < 16; u++) {
            const int r = u * 2 + srh;
            outb[(size_t)(i0 + rg * 32 + r) * NSP + j0 + sc] = stage[sc * 33 + r];
        }
    }

    __syncthreads();
    if (t < 128) {
        atomicAdd(&g_rowsum[b * NSP + i0 + t], srow[t]);
        atomicAdd(&g_colsum[b * NSP + j0 + t], scol[t]);
    }
}

// ---------------------------------------------------------------------------
// Kernel 2b: inverse sums (tiny)
// ---------------------------------------------------------------------------
__global__ void inv_kernel() {
    int i = blockIdx.x * 256 + threadIdx.x;
    g_invr[i] = 1.0f / g_rowsum[i];
    g_invc[i] = 1.0f / g_colsum[i];
}

// ---------------------------------------------------------------------------
// top-3 helpers
// ---------------------------------------------------------------------------
__device__ __forceinline__ void top3_push(float v, float& v0, float& v1, float& v2) {
    if (v > v2) {
        if (v > v1) {
            v2 = v1;
            if (v > v0) { v1 = v0; v0 = v; } else { v1 = v; }
        } else v2 = v;
    }
}
__device__ __forceinline__ void warp_reduce_top3(float& v0, float& v1, float& v2) {
    #pragma unroll
    for (int off = 16; off > 0; off >>= 1) {
        float u0 = __shfl_down_sync(0xFFFFFFFFu, v0, off);
        float u1 = __shfl_down_sync(0xFFFFFFFFu, v1, off);
        float u2 = __shfl_down_sync(0xFFFFFFFFu, v2, off);
        top3_push(u0, v0, v1, v2);
        top3_push(u1, v0, v1, v2);
        top3_push(u2, v0, v1, v2);
    }
}

// ---------------------------------------------------------------------------
// Kernel 3: finish — interleaved-role single launch [R10, measured 160us]
// ---------------------------------------------------------------------------
__global__ __launch_bounds__(256)
void finish_kernel(float* __restrict__ xcq, float* __restrict__ xcp,
                   float* __restrict__ valp) {
    __shared__ float tile[2][128][17];
    const int b  = blockIdx.y;
    const int bx = blockIdx.x;
    const int t  = threadIdx.x;
    const int w  = t >> 5, lane = t & 31;

    if (bx % 3 == 0) {
        // ---------------- row role ----------------
        const int ri = bx / 3;
        const int i  = ri * 8 + w;
        const float invr = g_invr[b * NSP + i];
        const float* invc = g_invc + b * NSP;
        const float* src = g_E + (size_t)b * BN2 + (size_t)i * NSP;
        float*       dst = xcq + (size_t)b * BN2 + (size_t)i * NSP;

        float v0 = -1e30f, v1 = -1e30f, v2 = -1e30f;
        for (int jb = lane * 4; jb < NSP; jb += 128) {
            float4 e  = *(const float4*)(src + jb);
            float4 ic = *(const float4*)(invc + jb);
            float x0 = e.x * e.x * invr * ic.x;
            float x1 = e.y * e.y * invr * ic.y;
            float x2 = e.z * e.z * invr * ic.z;
            float x3 = e.w * e.w * invr * ic.w;
            *(float4*)(dst + jb) = make_float4(x0, x1, x2, x3);
            top3_push(x0, v0, v1, v2);
            top3_push(x1, v0, v1, v2);
            top3_push(x2, v0, v1, v2);
            top3_push(x3, v0, v1, v2);
        }
        warp_reduce_top3(v0, v1, v2);
        if (lane == 0) {
            valp[b * 3 * NSP + 0 * NSP + i] = v0;
            valp[b * 3 * NSP + 1 * NSP + i] = v1;
            valp[b * 3 * NSP + 2 * NSP + i] = v2;
        }
    } else {
        // ---------------- col role ----------------
        const int ci = bx - 1 - bx / 3;
        const int j0 = (ci & 255) * 16;
        const int i0 = (ci >> 8) * 1024;
        const int ry = ci >> 8;
        const int lrow = t >> 4, lcol = t & 15;
        const float invc_l = g_invc[b * NSP + j0 + lcol];
        const float* invr = g_invr + b * NSP;
        const float* src = g_E + (size_t)b * BN2;
        float*       dst = xcp + (size_t)b * BN2;

        float c0[2], c1[2], c2[2];
        #pragma unroll
        for (int k = 0; k < 2; k++) { c0[k] = -1e30f; c1[k] = -1e30f; c2[k] = -1e30f; }

        auto load = [&](int ic, int bf) {
            #pragma unroll
            for (int u = 0; u < 8; u++) {
                int r = lrow + u * 16;
                float e = src[(size_t)(ic + r) * NSP + j0 + lcol];
                tile[bf][r][lcol] = e * e * invr[ic + r] * invc_l;
            }
        };

        load(i0, 0);
        int bf = 0;

        #pragma unroll 1
        for (int ic = i0; ic < i0 + 1024; ic += 128) {
            __syncthreads();
            if (ic + 128 < i0 + 1024) load(ic + 128, bf ^ 1);

            #pragma unroll
            for (int cc = 0; cc < 2; cc++) {
                const int col = w * 2 + cc;
                #pragma unroll
                for (int g2 = 0; g2 < 4; g2++) {
                    float v = tile[bf][g2 * 32 + lane][col];
                    dst[(size_t)(j0 + col) * NSP + ic + g2 * 32 + lane] = v;
                    top3_push(v, c0[cc], c1[cc], c2[cc]);
                }
            }
            bf ^= 1;
        }

        #pragma unroll
        for (int cc = 0; cc < 2; cc++) {
            float v0 = c0[cc], v1 = c1[cc], v2 = c2[cc];
            warp_reduce_top3(v0, v1, v2);
            if (lane == 0) {
                const int base = (b * 4 + ry) * 3;
                const int j = j0 + w * 2 + cc;
                g_cpart[(base + 0) * NSP + j] = v0;
                g_cpart[(base + 1) * NSP + j] = v1;
                g_cpart[(base + 2) * NSP + j] = v2;
            }
        }
    }
}

// ---------------------------------------------------------------------------
// Kernel 4: merge 4 column partials -> valq
// ---------------------------------------------------------------------------
__global__ __launch_bounds__(256)
void valq_reduce_kernel(float* __restrict__ valq) {
    const int b = blockIdx.y;
    const int j = blockIdx.x * 256 + threadIdx.x;
    float v0 = -1e30f, v1 = -1e30f, v2 = -1e30f;
    #pragma unroll
    for (int p = 0; p < 4; p++) {
        const int base = (b * 4 + p) * 3;
        top3_push(g_cpart[(base + 0) * NSP + j], v0, v1, v2);
        top3_push(g_cpart[(base + 1) * NSP + j], v0, v1, v2);
        top3_push(g_cpart[(base + 2) * NSP + j], v0, v1, v2);
    }
    valq[b * 3 * NSP + 0 * NSP + j] = v0;
    valq[b * 3 * NSP + 1 * NSP + j] = v1;
    valq[b * 3 * NSP + 2 * NSP + j] = v2;
}

// ---------------------------------------------------------------------------
extern "C" void kernel_launch(void* const* d_in, const int* in_sizes, int n_in,
                              void* d_out, int out_size) {
    const float* xp    = (const float*)d_in[0];
    const float* xq    = (const float*)d_in[1];
    const float* alpha = (const float*)d_in[2];

    float* valp = (float*)d_out;
    float* valq = valp + BATCH * 3 * NSP;
    float* xcp  = valq + BATCH * 3 * NSP;
    float* xcq  = xcp + (size_t)BATCH * BN2;

    cudaFuncSetAttribute(gemm_exp_kernel,
                         cudaFuncAttributeMaxDynamicSharedMemorySize, SMEM_TOTAL);

    prep_kernel<<<dim3(128, BATCH, 2), 256>>>(xp, xq);
    gemm_exp_kernel<<<dim3(32, 32, BATCH), 256, SMEM_TOTAL>>>(alpha);
    inv_kernel<<<64, 256>>>();
    finish_kernel<<<dim3(1536, BATCH), 256>>>(xcq, xcp, valp);
    valq_reduce_kernel<<<dim3(16, BATCH), 256>>>(valq);
}

// round 13
// speedup vs baseline: 1.6992x; 1.6992x over previous
#include <cuda_runtime.h>
#include <cuda_bf16.h>
#include <math.h>
#include <cstdint>

#define BATCH 4
#define CDIM  256
#define NSP   4096
#define BN2   16777216
#define KTOT  768          // [hi | lo | hi] x [hi | hi | lo]
#define NCHUNK 12          // K chunks of 64

// ---------------------------------------------------------------------------
// Device scratch
// ---------------------------------------------------------------------------
__device__ float g_rowsum[BATCH * NSP];
__device__ float g_colsum[BATCH * NSP];
__device__ float g_invr[BATCH * NSP];
__device__ float g_invc[BATCH * NSP];
__device__ __nv_bfloat16 g_P[(size_t)BATCH * NSP * KTOT];
__device__ __nv_bfloat16 g_Q[(size_t)BATCH * NSP * KTOT];
__device__ float g_E[(size_t)BATCH * BN2];       // e = exp(alpha*dot)
__device__ float g_cpart[BATCH * 4 * 3 * NSP];   // [b][rowquarter][3][col]

// ---------------------------------------------------------------------------
// PTX helpers (sm_80-compatible: cp.async, ldmatrix, mma.sync)
// ---------------------------------------------------------------------------
__device__ __forceinline__ uint32_t smem_u32(const void* p) {
    uint32_t a;
    asm("{ .reg .u64 t; cvta.to.shared.u64 t, %1; cvt.u32.u64 %0, t; }"
        : "=r"(a) : "l"(p));
    return a;
}
__device__ __forceinline__ void cp16(uint32_t s, const void* g) {
    asm volatile("cp.async.cg.shared.global [%0], [%1], 16;" :: "r"(s), "l"(g));
}
__device__ __forceinline__ void cp_commit() {
    asm volatile("cp.async.commit_group;");
}
template <int N>
__device__ __forceinline__ void cp_wait() {
    asm volatile("cp.async.wait_group %0;" :: "n"(N));
}
__device__ __forceinline__ void ldmx4(uint32_t* r, uint32_t addr) {
    asm volatile("ldmatrix.sync.aligned.m8n8.x4.shared.b16 {%0,%1,%2,%3}, [%4];"
                 : "=r"(r[0]), "=r"(r[1]), "=r"(r[2]), "=r"(r[3]) : "r"(addr));
}
__device__ __forceinline__ void mma16816(float* d, const uint32_t* a, const uint32_t* b) {
    asm volatile(
        "mma.sync.aligned.m16n8k16.row.col.f32.bf16.bf16.f32 "
        "{%0,%1,%2,%3}, {%4,%5,%6,%7}, {%8,%9}, {%0,%1,%2,%3};"
        : "+f"(d[0]), "+f"(d[1]), "+f"(d[2]), "+f"(d[3])
        : "r"(a[0]), "r"(a[1]), "r"(a[2]), "r"(a[3]), "r"(b[0]), "r"(b[1]));
}

// ---------------------------------------------------------------------------
// Kernel 1: prep — L2-normalize over channels, bf16 hi/lo split, K-major
// [m][768]. Also zeroes the sum accumulators.
// ---------------------------------------------------------------------------
__global__ __launch_bounds__(256)
void prep_kernel(const float* __restrict__ xp, const float* __restrict__ xq) {
    __shared__ float tile[32][257];
    const int m0 = blockIdx.x * 32;
    const int b  = blockIdx.y;
    const int t  = threadIdx.x;
    const int w  = t >> 5, lane = t & 31;
    const bool isP = (blockIdx.z == 0);
    const float* src = isP ? xp : xq;
    __nv_bfloat16* dst = isP ? g_P : g_Q;

    if (blockIdx.z == 0 && blockIdx.y == 0 && blockIdx.x < 64) {
        int idx = blockIdx.x * 256 + t;
        g_rowsum[idx] = 0.0f;
        g_colsum[idx] = 0.0f;
    }

    #pragma unroll 8
    for (int it = 0; it < 32; it++) {
        int c = w + it * 8;
        tile[lane][c] = src[((size_t)b * CDIM + c) * NSP + m0 + lane];
    }
    __syncthreads();

    #pragma unroll
    for (int r = 0; r < 4; r++) {
        int row = w * 4 + r;
        float s = 0.0f;
        #pragma unroll
        for (int k = 0; k < 8; k++) {
            float v = tile[row][lane + 32 * k];
            s = fmaf(v, v, s);
        }
        #pragma unroll
        for (int off = 16; off > 0; off >>= 1)
            s += __shfl_down_sync(0xFFFFFFFFu, s, off);
        float invn = 1.0f / fmaxf(sqrtf(__shfl_sync(0xFFFFFFFFu, s, 0)), 1e-12f);

        size_t obase = ((size_t)b * NSP + m0 + row) * KTOT;
        #pragma unroll
        for (int k = 0; k < 8; k++) {
            int c = lane + 32 * k;
            float v = tile[row][c] * invn;
            __nv_bfloat16 hi = __float2bfloat16(v);
            __nv_bfloat16 lo = __float2bfloat16(v - __bfloat162float(hi));
            dst[obase + c] = hi;
            dst[obase + 256 + c] = isP ? lo : hi;
            dst[obase + 512 + c] = isP ? hi : lo;
        }
    }
}

// ---------------------------------------------------------------------------
// Kernel 2: HMMA GEMM (128x128, K=768, 2 CTA/SM, double buffer) [R10 config]
// + exp epilogue -> g_E. Per-batch launch (b as parameter).
// ---------------------------------------------------------------------------
#define SMEM_BUFS  1024
#define SMEM_TOTAL (1024 + 4 * 16384)

__global__ __launch_bounds__(256, 2)
void gemm_exp_kernel(const float* __restrict__ alpha_p, int b) {
    extern __shared__ char smem[];
    const uint32_t sbase = smem_u32(smem);
    float* srow = (float*)smem;
    float* scol = (float*)(smem + 512);

    const int t = threadIdx.x;
    const int w = t >> 5, lane = t & 31;
    const int i0 = blockIdx.y * 128;
    const int j0 = blockIdx.x * 128;

    if (t < 128) { srow[t] = 0.0f; scol[t] = 0.0f; }

    const __nv_bfloat16* Abase = g_P + ((size_t)b * NSP + i0) * KTOT;
    const __nv_bfloat16* Bbase = g_Q + ((size_t)b * NSP + j0) * KTOT;

    auto load_chunk = [&](int c, int buf) {
        uint32_t aS = sbase + SMEM_BUFS + buf * 32768;
        uint32_t bS = aS + 16384;
        #pragma unroll
        for (int u = 0; u < 4; u++) {
            int f = t + 256 * u;
            uint32_t row = f >> 3, seg = f & 7;
            uint32_t off = row * 128 + ((seg ^ (row & 7)) << 4);
            cp16(aS + off, Abase + (size_t)row * KTOT + c * 64 + seg * 8);
            cp16(bS + off, Bbase + (size_t)row * KTOT + c * 64 + seg * 8);
        }
    };

    const int wm = w >> 2, wn = w & 3;
    const int r16 = lane & 15, ahi = lane >> 4;
    const int bn  = (lane & 7) + ((lane >> 4) << 3);
    const int bkl = (lane >> 3) & 1;

    float d[4][4][4] = {};

    load_chunk(0, 0);
    cp_commit();

    #pragma unroll 1
    for (int c = 0; c < NCHUNK; c++) {
        if (c < NCHUNK - 1) { load_chunk(c + 1, (c + 1) & 1); cp_commit(); }
        if (c < NCHUNK - 1) cp_wait<1>(); else cp_wait<0>();
        __syncthreads();

        uint32_t aS = sbase + SMEM_BUFS + (c & 1) * 32768;
        uint32_t bS = aS + 16384;

        #pragma unroll
        for (int kk = 0; kk < 4; kk++) {
            uint32_t afr[4][4];
            #pragma unroll
            for (int mt = 0; mt < 4; mt++) {
                uint32_t row = wm * 64 + mt * 16 + r16;
                uint32_t col = (((2 * kk + ahi) ^ (r16 & 7)) << 4);
                ldmx4(afr[mt], aS + row * 128 + col);
            }
            uint32_t bfr[4][2];
            #pragma unroll
            for (int np = 0; np < 2; np++) {
                uint32_t nrow = wn * 32 + np * 16 + bn;
                uint32_t col = (((2 * kk + bkl) ^ (bn & 7)) << 4);
                uint32_t q[4];
                ldmx4(q, bS + nrow * 128 + col);
                bfr[2 * np][0] = q[0]; bfr[2 * np][1] = q[1];
                bfr[2 * np + 1][0] = q[2]; bfr[2 * np + 1][1] = q[3];
            }
            #pragma unroll
            for (int mt = 0; mt < 4; mt++)
                #pragma unroll
                for (int nt = 0; nt < 4; nt++)
                    mma16816(d[mt][nt], afr[mt], bfr[nt]);
        }
        __syncthreads();
    }

    const float alpha = __ldg(alpha_p);
    const int g = lane >> 2, tg = lane & 3;
    float csum[4][2] = {};
    float* outb = g_E + (size_t)b * BN2;

    #pragma unroll
    for (int mt = 0; mt < 4; mt++) {
        float rs0 = 0.0f, rs1 = 0.0f;
        const int row0 = i0 + wm * 64 + mt * 16 + g;
        #pragma unroll
        for (int nt = 0; nt < 4; nt++) {
            float e0 = __expf(d[mt][nt][0] * alpha);
            float e1 = __expf(d[mt][nt][1] * alpha);
            float e2 = __expf(d[mt][nt][2] * alpha);
            float e3 = __expf(d[mt][nt][3] * alpha);
            rs0 += e0 + e1; rs1 += e2 + e3;
            csum[nt][0] += e0 + e2; csum[nt][1] += e1 + e3;
            const int colg = j0 + wn * 32 + nt * 8 + tg * 2;
            *(float2*)(outb + (size_t)row0 * NSP + colg)       = make_float2(e0, e1);
            *(float2*)(outb + (size_t)(row0 + 8) * NSP + colg) = make_float2(e2, e3);
        }
        rs0 += __shfl_xor_sync(0xFFFFFFFFu, rs0, 1);
        rs0 += __shfl_xor_sync(0xFFFFFFFFu, rs0, 2);
        rs1 += __shfl_xor_sync(0xFFFFFFFFu, rs1, 1);
        rs1 += __shfl_xor_sync(0xFFFFFFFFu, rs1, 2);
        if (tg == 0) {
            atomicAdd(&srow[wm * 64 + mt * 16 + g],     rs0);
            atomicAdd(&srow[wm * 64 + mt * 16 + g + 8], rs1);
        }
    }
    #pragma unroll
    for (int nt = 0; nt < 4; nt++)
        #pragma unroll
        for (int cc = 0; cc < 2; cc++) {
            float v = csum[nt][cc];
            v += __shfl_xor_sync(0xFFFFFFFFu, v, 4);
            v += __shfl_xor_sync(0xFFFFFFFFu, v, 8);
            v += __shfl_xor_sync(0xFFFFFFFFu, v, 16);
            if (g == 0) atomicAdd(&scol[wn * 32 + nt * 8 + tg * 2 + cc], v);
        }
    __syncthreads();
    if (t < 128) {
        atomicAdd(&g_rowsum[b * NSP + i0 + t], srow[t]);
        atomicAdd(&g_colsum[b * NSP + j0 + t], scol[t]);
    }
}

// ---------------------------------------------------------------------------
// Kernel 2b: inverse sums for one batch (tiny)
// ---------------------------------------------------------------------------
__global__ void inv_kernel(int b) {
    int i = b * NSP + blockIdx.x * 256 + threadIdx.x;
    g_invr[i] = 1.0f / g_rowsum[i];
    g_invc[i] = 1.0f / g_colsum[i];
}

// ---------------------------------------------------------------------------
// top-3 helpers
// ---------------------------------------------------------------------------
__device__ __forceinline__ void top3_push(float v, float& v0, float& v1, float& v2) {
    if (v > v2) {
        if (v > v1) {
            v2 = v1;
            if (v > v0) { v1 = v0; v0 = v; } else { v1 = v; }
        } else v2 = v;
    }
}
__device__ __forceinline__ void warp_reduce_top3(float& v0, float& v1, float& v2) {
    #pragma unroll
    for (int off = 16; off > 0; off >>= 1) {
        float u0 = __shfl_down_sync(0xFFFFFFFFu, v0, off);
        float u1 = __shfl_down_sync(0xFFFFFFFFu, v1, off);
        float u2 = __shfl_down_sync(0xFFFFFFFFu, v2, off);
        top3_push(u0, v0, v1, v2);
        top3_push(u1, v0, v1, v2);
        top3_push(u2, v0, v1, v2);
    }
}

// ---------------------------------------------------------------------------
// Kernel 3: finish — interleaved-role single launch, per batch. [R10 body]
// ---------------------------------------------------------------------------
__global__ __launch_bounds__(256)
void finish_kernel(float* __restrict__ xcq, float* __restrict__ xcp,
                   float* __restrict__ valp, int b) {
    __shared__ float tile[2][128][17];
    const int bx = blockIdx.x;
    const int t  = threadIdx.x;
    const int w  = t >> 5, lane = t & 31;

    if (bx % 3 == 0) {
        // ---------------- row role ----------------
        const int ri = bx / 3;
        const int i  = ri * 8 + w;
        const float invr = g_invr[b * NSP + i];
        const float* invc = g_invc + b * NSP;
        const float* src = g_E + (size_t)b * BN2 + (size_t)i * NSP;
        float*       dst = xcq + (size_t)b * BN2 + (size_t)i * NSP;

        float v0 = -1e30f, v1 = -1e30f, v2 = -1e30f;
        for (int jb = lane * 4; jb < NSP; jb += 128) {
            float4 e  = *(const float4*)(src + jb);
            float4 ic = *(const float4*)(invc + jb);
            float x0 = e.x * e.x * invr * ic.x;
            float x1 = e.y * e.y * invr * ic.y;
            float x2 = e.z * e.z * invr * ic.z;
            float x3 = e.w * e.w * invr * ic.w;
            *(float4*)(dst + jb) = make_float4(x0, x1, x2, x3);
            top3_push(x0, v0, v1, v2);
            top3_push(x1, v0, v1, v2);
            top3_push(x2, v0, v1, v2);
            top3_push(x3, v0, v1, v2);
        }
        warp_reduce_top3(v0, v1, v2);
        if (lane == 0) {
            valp[b * 3 * NSP + 0 * NSP + i] = v0;
            valp[b * 3 * NSP + 1 * NSP + i] = v1;
            valp[b * 3 * NSP + 2 * NSP + i] = v2;
        }
    } else {
        // ---------------- col role ----------------
        const int ci = bx - 1 - bx / 3;
        const int j0 = (ci & 255) * 16;
        const int i0 = (ci >> 8) * 1024;
        const int ry = ci >> 8;
        const int lrow = t >> 4, lcol = t & 15;
        const float invc_l = g_invc[b * NSP + j0 + lcol];
        const float* invr = g_invr + b * NSP;
        const float* src = g_E + (size_t)b * BN2;
        float*       dst = xcp + (size_t)b * BN2;

        float c0[2], c1[2], c2[2];
        #pragma unroll
        for (int k = 0; k < 2; k++) { c0[k] = -1e30f; c1[k] = -1e30f; c2[k] = -1e30f; }

        auto load = [&](int ic, int bf) {
            #pragma unroll
            for (int u = 0; u < 8; u++) {
                int r = lrow + u * 16;
                float e = src[(size_t)(ic + r) * NSP + j0 + lcol];
                tile[bf][r][lcol] = e * e * invr[ic + r] * invc_l;
            }
        };

        load(i0, 0);
        int bf = 0;

        #pragma unroll 1
        for (int ic = i0; ic < i0 + 1024; ic += 128) {
            __syncthreads();
            if (ic + 128 < i0 + 1024) load(ic + 128, bf ^ 1);

            #pragma unroll
            for (int cc = 0; cc < 2; cc++) {
                const int col = w * 2 + cc;
                #pragma unroll
                for (int g2 = 0; g2 < 4; g2++) {
                    float v = tile[bf][g2 * 32 + lane][col];
                    dst[(size_t)(j0 + col) * NSP + ic + g2 * 32 + lane] = v;
                    top3_push(v, c0[cc], c1[cc], c2[cc]);
                }
            }
            bf ^= 1;
        }

        #pragma unroll
        for (int cc = 0; cc < 2; cc++) {
            float v0 = c0[cc], v1 = c1[cc], v2 = c2[cc];
            warp_reduce_top3(v0, v1, v2);
            if (lane == 0) {
                const int base = (b * 4 + ry) * 3;
                const int j = j0 + w * 2 + cc;
                g_cpart[(base + 0) * NSP + j] = v0;
                g_cpart[(base + 1) * NSP + j] = v1;
                g_cpart[(base + 2) * NSP + j] = v2;
            }
        }
    }
}

// ---------------------------------------------------------------------------
// Kernel 4: merge 4 column partials -> valq
// ---------------------------------------------------------------------------
__global__ __launch_bounds__(256)
void valq_reduce_kernel(float* __restrict__ valq) {
    const int b = blockIdx.y;
    const int j = blockIdx.x * 256 + threadIdx.x;
    float v0 = -1e30f, v1 = -1e30f, v2 = -1e30f;
    #pragma unroll
    for (int p = 0; p < 4; p++) {
        const int base = (b * 4 + p) * 3;
        top3_push(g_cpart[(base + 0) * NSP + j], v0, v1, v2);
        top3_push(g_cpart[(base + 1) * NSP + j], v0, v1, v2);
        top3_push(g_cpart[(base + 2) * NSP + j], v0, v1, v2);
    }
    valq[b * 3 * NSP + 0 * NSP + j] = v0;
    valq[b * 3 * NSP + 1 * NSP + j] = v1;
    valq[b * 3 * NSP + 2 * NSP + j] = v2;
}

// ---------------------------------------------------------------------------
// Launch: per-batch pipeline across two streams so finish(b) overlaps
// gemm(b+1..). Streams/events lazily created on first (non-captured) call.
// ---------------------------------------------------------------------------
extern "C" void kernel_launch(void* const* d_in, const int* in_sizes, int n_in,
                              void* d_out, int out_size) {
    const float* xp    = (const float*)d_in[0];
    const float* xq    = (const float*)d_in[1];
    const float* alpha = (const float*)d_in[2];

    float* valp = (float*)d_out;
    float* valq = valp + BATCH * 3 * NSP;
    float* xcp  = valq + BATCH * 3 * NSP;
    float* xcq  = xcp + (size_t)BATCH * BN2;

    static cudaStream_t s2 = nullptr;
    static cudaEvent_t evg[BATCH] = {};
    static cudaEvent_t evf = nullptr;
    if (s2 == nullptr) {
        cudaStreamCreateWithFlags(&s2, cudaStreamNonBlocking);
        for (int i = 0; i < BATCH; i++)
            cudaEventCreateWithFlags(&evg[i], cudaEventDisableTiming);
        cudaEventCreateWithFlags(&evf, cudaEventDisableTiming);
    }

    cudaFuncSetAttribute(gemm_exp_kernel,
                         cudaFuncAttributeMaxDynamicSharedMemorySize, SMEM_TOTAL);

    prep_kernel<<<dim3(128, BATCH, 2), 256>>>(xp, xq);

    if (s2 != nullptr) {
        for (int b = 0; b < BATCH; b++) {
            gemm_exp_kernel<<<dim3(32, 32), 256, SMEM_TOTAL>>>(alpha, b);
            cudaEventRecord(evg[b], 0);
            cudaStreamWaitEvent(s2, evg[b], 0);
            inv_kernel<<<16, 256, 0, s2>>>(b);
            finish_kernel<<<1536, 256, 0, s2>>>(xcq, xcp, valp, b);
        }
        cudaEventRecord(evf, s2);
        cudaStreamWaitEvent(0, evf, 0);
    } else {
        // fallback: single-stream sequential (identical work)
        for (int b = 0; b < BATCH; b++) {
            gemm_exp_kernel<<<dim3(32, 32), 256, SMEM_TOTAL>>>(alpha, b);
            inv_kernel<<<16, 256>>>(b);
            finish_kernel<<<1536, 256>>>(xcq, xcp, valp, b);
        }
    }

    valq_reduce_kernel<<<dim3(16, BATCH), 256>>>(valq);
}

// round 14
// speedup vs baseline: 1.7458x; 1.0275x over previous
#include <cuda_runtime.h>
#include <cuda_bf16.h>
#include <math.h>
#include <cstdint>

#define BATCH 4
#define CDIM  256
#define NSP   4096
#define BN2   16777216
#define KTOT  768          // [hi | lo | hi] x [hi | hi | lo]
#define NCHUNK 12          // K chunks of 64

// ---------------------------------------------------------------------------
// Device scratch
// ---------------------------------------------------------------------------
__device__ float g_rowsum[BATCH * NSP];
__device__ float g_colsum[BATCH * NSP];
__device__ float g_invr[BATCH * NSP];
__device__ float g_invc[BATCH * NSP];
__device__ __nv_bfloat16 g_P[(size_t)BATCH * NSP * KTOT];
__device__ __nv_bfloat16 g_Q[(size_t)BATCH * NSP * KTOT];
__device__ float g_E[(size_t)BATCH * BN2];       // e = exp(alpha*dot)
__device__ float g_cpart[BATCH * 4 * 3 * NSP];   // [b][rowquarter][3][col]

// ---------------------------------------------------------------------------
// PTX helpers (sm_80-compatible: cp.async, ldmatrix, mma.sync)
// ---------------------------------------------------------------------------
__device__ __forceinline__ uint32_t smem_u32(const void* p) {
    uint32_t a;
    asm("{ .reg .u64 t; cvta.to.shared.u64 t, %1; cvt.u32.u64 %0, t; }"
        : "=r"(a) : "l"(p));
    return a;
}
__device__ __forceinline__ void cp16(uint32_t s, const void* g) {
    asm volatile("cp.async.cg.shared.global [%0], [%1], 16;" :: "r"(s), "l"(g));
}
__device__ __forceinline__ void cp_commit() {
    asm volatile("cp.async.commit_group;");
}
template <int N>
__device__ __forceinline__ void cp_wait() {
    asm volatile("cp.async.wait_group %0;" :: "n"(N));
}
__device__ __forceinline__ void ldmx4(uint32_t* r, uint32_t addr) {
    asm volatile("ldmatrix.sync.aligned.m8n8.x4.shared.b16 {%0,%1,%2,%3}, [%4];"
                 : "=r"(r[0]), "=r"(r[1]), "=r"(r[2]), "=r"(r[3]) : "r"(addr));
}
__device__ __forceinline__ void mma16816(float* d, const uint32_t* a, const uint32_t* b) {
    asm volatile(
        "mma.sync.aligned.m16n8k16.row.col.f32.bf16.bf16.f32 "
        "{%0,%1,%2,%3}, {%4,%5,%6,%7}, {%8,%9}, {%0,%1,%2,%3};"
        : "+f"(d[0]), "+f"(d[1]), "+f"(d[2]), "+f"(d[3])
        : "r"(a[0]), "r"(a[1]), "r"(a[2]), "r"(a[3]), "r"(b[0]), "r"(b[1]));
}

// ---------------------------------------------------------------------------
// Kernel 1: prep — L2-normalize over channels, bf16 hi/lo split, K-major
// [m][768]. Also zeroes the sum accumulators.
// ---------------------------------------------------------------------------
__global__ __launch_bounds__(256)
void prep_kernel(const float* __restrict__ xp, const float* __restrict__ xq) {
    __shared__ float tile[32][257];
    const int m0 = blockIdx.x * 32;
    const int b  = blockIdx.y;
    const int t  = threadIdx.x;
    const int w  = t >> 5, lane = t & 31;
    const bool isP = (blockIdx.z == 0);
    const float* src = isP ? xp : xq;
    __nv_bfloat16* dst = isP ? g_P : g_Q;

    if (blockIdx.z == 0 && blockIdx.y == 0 && blockIdx.x < 64) {
        int idx = blockIdx.x * 256 + t;
        g_rowsum[idx] = 0.0f;
        g_colsum[idx] = 0.0f;
    }

    #pragma unroll 8
    for (int it = 0; it < 32; it++) {
        int c = w + it * 8;
        tile[lane][c] = src[((size_t)b * CDIM + c) * NSP + m0 + lane];
    }
    __syncthreads();

    #pragma unroll
    for (int r = 0; r < 4; r++) {
        int row = w * 4 + r;
        float s = 0.0f;
        #pragma unroll
        for (int k = 0; k < 8; k++) {
            float v = tile[row][lane + 32 * k];
            s = fmaf(v, v, s);
        }
        #pragma unroll
        for (int off = 16; off > 0; off >>= 1)
            s += __shfl_down_sync(0xFFFFFFFFu, s, off);
        float invn = 1.0f / fmaxf(sqrtf(__shfl_sync(0xFFFFFFFFu, s, 0)), 1e-12f);

        size_t obase = ((size_t)b * NSP + m0 + row) * KTOT;
        #pragma unroll
        for (int k = 0; k < 8; k++) {
            int c = lane + 32 * k;
            float v = tile[row][c] * invn;
            __nv_bfloat16 hi = __float2bfloat16(v);
            __nv_bfloat16 lo = __float2bfloat16(v - __bfloat162float(hi));
            dst[obase + c] = hi;
            dst[obase + 256 + c] = isP ? lo : hi;
            dst[obase + 512 + c] = isP ? hi : lo;
        }
    }
}

// ---------------------------------------------------------------------------
// Kernel 2: HMMA GEMM (128x128, K=768, 2 CTA/SM, double buffer) [R10 config]
// + exp epilogue -> g_E; accumulates row/col sums.
// ---------------------------------------------------------------------------
#define SMEM_BUFS  1024
#define SMEM_TOTAL (1024 + 4 * 16384)

__global__ __launch_bounds__(256, 2)
void gemm_exp_kernel(const float* __restrict__ alpha_p) {
    extern __shared__ char smem[];
    const uint32_t sbase = smem_u32(smem);
    float* srow = (float*)smem;
    float* scol = (float*)(smem + 512);

    const int t = threadIdx.x;
    const int w = t >> 5, lane = t & 31;
    const int b  = blockIdx.z;
    const int i0 = blockIdx.y * 128;
    const int j0 = blockIdx.x * 128;

    if (t < 128) { srow[t] = 0.0f; scol[t] = 0.0f; }

    const __nv_bfloat16* Abase = g_P + ((size_t)b * NSP + i0) * KTOT;
    const __nv_bfloat16* Bbase = g_Q + ((size_t)b * NSP + j0) * KTOT;

    auto load_chunk = [&](int c, int buf) {
        uint32_t aS = sbase + SMEM_BUFS + buf * 32768;
        uint32_t bS = aS + 16384;
        #pragma unroll
        for (int u = 0; u < 4; u++) {
            int f = t + 256 * u;
            uint32_t row = f >> 3, seg = f & 7;
            uint32_t off = row * 128 + ((seg ^ (row & 7)) << 4);
            cp16(aS + off, Abase + (size_t)row * KTOT + c * 64 + seg * 8);
            cp16(bS + off, Bbase + (size_t)row * KTOT + c * 64 + seg * 8);
        }
    };

    const int wm = w >> 2, wn = w & 3;
    const int r16 = lane & 15, ahi = lane >> 4;
    const int bn  = (lane & 7) + ((lane >> 4) << 3);
    const int bkl = (lane >> 3) & 1;

    float d[4][4][4] = {};

    load_chunk(0, 0);
    cp_commit();

    #pragma unroll 1
    for (int c = 0; c < NCHUNK; c++) {
        if (c < NCHUNK - 1) { load_chunk(c + 1, (c + 1) & 1); cp_commit(); }
        if (c < NCHUNK - 1) cp_wait<1>(); else cp_wait<0>();
        __syncthreads();

        uint32_t aS = sbase + SMEM_BUFS + (c & 1) * 32768;
        uint32_t bS = aS + 16384;

        #pragma unroll
        for (int kk = 0; kk < 4; kk++) {
            uint32_t afr[4][4];
            #pragma unroll
            for (int mt = 0; mt < 4; mt++) {
                uint32_t row = wm * 64 + mt * 16 + r16;
                uint32_t col = (((2 * kk + ahi) ^ (r16 & 7)) << 4);
                ldmx4(afr[mt], aS + row * 128 + col);
            }
            uint32_t bfr[4][2];
            #pragma unroll
            for (int np = 0; np < 2; np++) {
                uint32_t nrow = wn * 32 + np * 16 + bn;
                uint32_t col = (((2 * kk + bkl) ^ (bn & 7)) << 4);
                uint32_t q[4];
                ldmx4(q, bS + nrow * 128 + col);
                bfr[2 * np][0] = q[0]; bfr[2 * np][1] = q[1];
                bfr[2 * np + 1][0] = q[2]; bfr[2 * np + 1][1] = q[3];
            }
            #pragma unroll
            for (int mt = 0; mt < 4; mt++)
                #pragma unroll
                for (int nt = 0; nt < 4; nt++)
                    mma16816(d[mt][nt], afr[mt], bfr[nt]);
        }
        __syncthreads();
    }

    const float alpha = __ldg(alpha_p);
    const int g = lane >> 2, tg = lane & 3;
    float csum[4][2] = {};
    float* outb = g_E + (size_t)b * BN2;

    #pragma unroll
    for (int mt = 0; mt < 4; mt++) {
        float rs0 = 0.0f, rs1 = 0.0f;
        const int row0 = i0 + wm * 64 + mt * 16 + g;
        #pragma unroll
        for (int nt = 0; nt < 4; nt++) {
            float e0 = __expf(d[mt][nt][0] * alpha);
            float e1 = __expf(d[mt][nt][1] * alpha);
            float e2 = __expf(d[mt][nt][2] * alpha);
            float e3 = __expf(d[mt][nt][3] * alpha);
            rs0 += e0 + e1; rs1 += e2 + e3;
            csum[nt][0] += e0 + e2; csum[nt][1] += e1 + e3;
            const int colg = j0 + wn * 32 + nt * 8 + tg * 2;
            *(float2*)(outb + (size_t)row0 * NSP + colg)       = make_float2(e0, e1);
            *(float2*)(outb + (size_t)(row0 + 8) * NSP + colg) = make_float2(e2, e3);
        }
        rs0 += __shfl_xor_sync(0xFFFFFFFFu, rs0, 1);
        rs0 += __shfl_xor_sync(0xFFFFFFFFu, rs0, 2);
        rs1 += __shfl_xor_sync(0xFFFFFFFFu, rs1, 1);
        rs1 += __shfl_xor_sync(0xFFFFFFFFu, rs1, 2);
        if (tg == 0) {
            atomicAdd(&srow[wm * 64 + mt * 16 + g],     rs0);
            atomicAdd(&srow[wm * 64 + mt * 16 + g + 8], rs1);
        }
    }
    #pragma unroll
    for (int nt = 0; nt < 4; nt++)
        #pragma unroll
        for (int cc = 0; cc < 2; cc++) {
            float v = csum[nt][cc];
            v += __shfl_xor_sync(0xFFFFFFFFu, v, 4);
            v += __shfl_xor_sync(0xFFFFFFFFu, v, 8);
            v += __shfl_xor_sync(0xFFFFFFFFu, v, 16);
            if (g == 0) atomicAdd(&scol[wn * 32 + nt * 8 + tg * 2 + cc], v);
        }
    __syncthreads();
    if (t < 128) {
        atomicAdd(&g_rowsum[b * NSP + i0 + t], srow[t]);
        atomicAdd(&g_colsum[b * NSP + j0 + t], scol[t]);
    }
}

// ---------------------------------------------------------------------------
// Kernel 2b: inverse sums (tiny)
// ---------------------------------------------------------------------------
__global__ void inv_kernel() {
    int i = blockIdx.x * 256 + threadIdx.x;
    g_invr[i] = 1.0f / g_rowsum[i];
    g_invc[i] = 1.0f / g_colsum[i];
}

// ---------------------------------------------------------------------------
// top-3 helpers
// ---------------------------------------------------------------------------
__device__ __forceinline__ void top3_push(float v, float& v0, float& v1, float& v2) {
    if (v > v2) {
        if (v > v1) {
            v2 = v1;
            if (v > v0) { v1 = v0; v0 = v; } else { v1 = v; }
        } else v2 = v;
    }
}
__device__ __forceinline__ void warp_reduce_top3(float& v0, float& v1, float& v2) {
    #pragma unroll
    for (int off = 16; off > 0; off >>= 1) {
        float u0 = __shfl_down_sync(0xFFFFFFFFu, v0, off);
        float u1 = __shfl_down_sync(0xFFFFFFFFu, v1, off);
        float u2 = __shfl_down_sync(0xFFFFFFFFu, v2, off);
        top3_push(u0, v0, v1, v2);
        top3_push(u1, v0, v1, v2);
        top3_push(u2, v0, v1, v2);
    }
}

// ---------------------------------------------------------------------------
// Kernel 3: finish — interleaved roles, QUARTER-GROUPED for L2 locality.
// Per batch 1536 CTAs in 4 groups of 384 (one per 1024-row quarter of g_E):
//   within group: r = bx % 384; r%3==0 -> row role (128 CTAs, rows of this
//   quarter), else col role (256 CTAs, 16-col strip x this quarter).
// Both roles stream the SAME 64MB quarter of g_E concurrently -> L2 reuse.
// ---------------------------------------------------------------------------
__global__ __launch_bounds__(256)
void finish_kernel(float* __restrict__ xcq, float* __restrict__ xcp,
                   float* __restrict__ valp) {
    __shared__ float tile[2][128][17];
    const int b  = blockIdx.y;
    const int bx = blockIdx.x;
    const int t  = threadIdx.x;
    const int w  = t >> 5, lane = t & 31;
    const int q  = bx / 384;              // quarter 0..3
    const int r  = bx % 384;

    if (r % 3 == 0) {
        // ---------------- row role: rows of quarter q ----------------
        const int ri = q * 128 + r / 3;   // 0..511
        const int i  = ri * 8 + w;
        const float invr = g_invr[b * NSP + i];
        const float* invc = g_invc + b * NSP;
        const float* src = g_E + (size_t)b * BN2 + (size_t)i * NSP;
        float*       dst = xcq + (size_t)b * BN2 + (size_t)i * NSP;

        float v0 = -1e30f, v1 = -1e30f, v2 = -1e30f;
        for (int jb = lane * 4; jb < NSP; jb += 128) {
            float4 e  = *(const float4*)(src + jb);
            float4 ic = *(const float4*)(invc + jb);
            float x0 = e.x * e.x * invr * ic.x;
            float x1 = e.y * e.y * invr * ic.y;
            float x2 = e.z * e.z * invr * ic.z;
            float x3 = e.w * e.w * invr * ic.w;
            *(float4*)(dst + jb) = make_float4(x0, x1, x2, x3);
            top3_push(x0, v0, v1, v2);
            top3_push(x1, v0, v1, v2);
            top3_push(x2, v0, v1, v2);
            top3_push(x3, v0, v1, v2);
        }
        warp_reduce_top3(v0, v1, v2);
        if (lane == 0) {
            valp[b * 3 * NSP + 0 * NSP + i] = v0;
            valp[b * 3 * NSP + 1 * NSP + i] = v1;
            valp[b * 3 * NSP + 2 * NSP + i] = v2;
        }
    } else {
        // ---------------- col role: 16-col strip x quarter q ----------------
        const int ci = r - 1 - r / 3;     // 0..255 within quarter
        const int j0 = ci * 16;
        const int i0 = q * 1024;
        const int lrow = t >> 4, lcol = t & 15;
        const float invc_l = g_invc[b * NSP + j0 + lcol];
        const float* invr = g_invr + b * NSP;
        const float* src = g_E + (size_t)b * BN2;
        float*       dst = xcp + (size_t)b * BN2;

        float c0[2], c1[2], c2[2];
        #pragma unroll
        for (int k = 0; k < 2; k++) { c0[k] = -1e30f; c1[k] = -1e30f; c2[k] = -1e30f; }

        auto load = [&](int ic, int bf) {
            #pragma unroll
            for (int u = 0; u < 8; u++) {
                int rr = lrow + u * 16;
                float e = src[(size_t)(ic + rr) * NSP + j0 + lcol];
                tile[bf][rr][lcol] = e * e * invr[ic + rr] * invc_l;
            }
        };

        load(i0, 0);
        int bf = 0;

        #pragma unroll 1
        for (int ic = i0; ic < i0 + 1024; ic += 128) {
            __syncthreads();
            if (ic + 128 < i0 + 1024) load(ic + 128, bf ^ 1);

            #pragma unroll
            for (int cc = 0; cc < 2; cc++) {
                const int col = w * 2 + cc;
                #pragma unroll
                for (int g2 = 0; g2 < 4; g2++) {
                    float v = tile[bf][g2 * 32 + lane][col];
                    dst[(size_t)(j0 + col) * NSP + ic + g2 * 32 + lane] = v;
                    top3_push(v, c0[cc], c1[cc], c2[cc]);
                }
            }
            bf ^= 1;
        }

        #pragma unroll
        for (int cc = 0; cc < 2; cc++) {
            float v0 = c0[cc], v1 = c1[cc], v2 = c2[cc];
            warp_reduce_top3(v0, v1, v2);
            if (lane == 0) {
                const int base = (b * 4 + q) * 3;
                const int j = j0 + w * 2 + cc;
                g_cpart[(base + 0) * NSP + j] = v0;
                g_cpart[(base + 1) * NSP + j] = v1;
                g_cpart[(base + 2) * NSP + j] = v2;
            }
        }
    }
}

// ---------------------------------------------------------------------------
// Kernel 4: merge 4 column partials -> valq
// ---------------------------------------------------------------------------
__global__ __launch_bounds__(256)
void valq_reduce_kernel(float* __restrict__ valq) {
    const int b = blockIdx.y;
    const int j = blockIdx.x * 256 + threadIdx.x;
    float v0 = -1e30f, v1 = -1e30f, v2 = -1e30f;
    #pragma unroll
    for (int p = 0; p < 4; p++) {
        const int base = (b * 4 + p) * 3;
        top3_push(g_cpart[(base + 0) * NSP + j], v0, v1, v2);
        top3_push(g_cpart[(base + 1) * NSP + j], v0, v1, v2);
        top3_push(g_cpart[(base + 2) * NSP + j], v0, v1, v2);
    }
    valq[b * 3 * NSP + 0 * NSP + j] = v0;
    valq[b * 3 * NSP + 1 * NSP + j] = v1;
    valq[b * 3 * NSP + 2 * NSP + j] = v2;
}

// ---------------------------------------------------------------------------
extern "C" void kernel_launch(void* const* d_in, const int* in_sizes, int n_in,
                              void* d_out, int out_size) {
    const float* xp    = (const float*)d_in[0];
    const float* xq    = (const float*)d_in[1];
    const float* alpha = (const float*)d_in[2];

    float* valp = (float*)d_out;
    float* valq = valp + BATCH * 3 * NSP;
    float* xcp  = valq + BATCH * 3 * NSP;
    float* xcq  = xcp + (size_t)BATCH * BN2;

    cudaFuncSetAttribute(gemm_exp_kernel,
                         cudaFuncAttributeMaxDynamicSharedMemorySize, SMEM_TOTAL);

    prep_kernel<<<dim3(128, BATCH, 2), 256>>>(xp, xq);
    gemm_exp_kernel<<<dim3(32, 32, BATCH), 256, SMEM_TOTAL>>>(alpha);
    inv_kernel<<<64, 256>>>();
    finish_kernel<<<dim3(1536, BATCH), 256>>>(xcq, xcp, valp);
    valq_reduce_kernel<<<dim3(16, BATCH), 256>>>(valq);
}

// round 15
// speedup vs baseline: 1.7586x; 1.0073x over previous
#include <cuda_runtime.h>
#include <cuda_bf16.h>
#include <math.h>
#include <cstdint>

#define BATCH 4
#define CDIM  256
#define NSP   4096
#define BN2   16777216
#define KTOT  768          // [hi | lo | hi] x [hi | hi | lo]
#define NCHUNK 12          // K chunks of 64

// ---------------------------------------------------------------------------
// Device scratch
// ---------------------------------------------------------------------------
__device__ float g_rowsum[BATCH * NSP];
__device__ float g_colsum[BATCH * NSP];
__device__ float g_invr[BATCH * NSP];
__device__ float g_invc[BATCH * NSP];
__device__ __nv_bfloat16 g_P[(size_t)BATCH * NSP * KTOT];
__device__ __nv_bfloat16 g_Q[(size_t)BATCH * NSP * KTOT];
__device__ float g_E[(size_t)BATCH * BN2];       // e = exp(alpha*dot)
__device__ float g_cpart[BATCH * 4 * 3 * NSP];   // [b][rowquarter][3][col]

// ---------------------------------------------------------------------------
// PTX helpers (sm_80-compatible: cp.async, ldmatrix, mma.sync)
// ---------------------------------------------------------------------------
__device__ __forceinline__ uint32_t smem_u32(const void* p) {
    uint32_t a;
    asm("{ .reg .u64 t; cvta.to.shared.u64 t, %1; cvt.u32.u64 %0, t; }"
        : "=r"(a) : "l"(p));
    return a;
}
__device__ __forceinline__ void cp16(uint32_t s, const void* g) {
    asm volatile("cp.async.cg.shared.global [%0], [%1], 16;" :: "r"(s), "l"(g));
}
__device__ __forceinline__ void cp_commit() {
    asm volatile("cp.async.commit_group;");
}
template <int N>
__device__ __forceinline__ void cp_wait() {
    asm volatile("cp.async.wait_group %0;" :: "n"(N));
}
__device__ __forceinline__ void ldmx4(uint32_t* r, uint32_t addr) {
    asm volatile("ldmatrix.sync.aligned.m8n8.x4.shared.b16 {%0,%1,%2,%3}, [%4];"
                 : "=r"(r[0]), "=r"(r[1]), "=r"(r[2]), "=r"(r[3]) : "r"(addr));
}
__device__ __forceinline__ void mma16816(float* d, const uint32_t* a, const uint32_t* b) {
    asm volatile(
        "mma.sync.aligned.m16n8k16.row.col.f32.bf16.bf16.f32 "
        "{%0,%1,%2,%3}, {%4,%5,%6,%7}, {%8,%9}, {%0,%1,%2,%3};"
        : "+f"(d[0]), "+f"(d[1]), "+f"(d[2]), "+f"(d[3])
        : "r"(a[0]), "r"(a[1]), "r"(a[2]), "r"(a[3]), "r"(b[0]), "r"(b[1]));
}

// ---------------------------------------------------------------------------
// Kernel 1: prep — L2-normalize over channels, bf16 hi/lo split, K-major
// [m][768]. Also zeroes the sum accumulators.
// ---------------------------------------------------------------------------
__global__ __launch_bounds__(256)
void prep_kernel(const float* __restrict__ xp, const float* __restrict__ xq) {
    __shared__ float tile[32][257];
    const int m0 = blockIdx.x * 32;
    const int b  = blockIdx.y;
    const int t  = threadIdx.x;
    const int w  = t >> 5, lane = t & 31;
    const bool isP = (blockIdx.z == 0);
    const float* src = isP ? xp : xq;
    __nv_bfloat16* dst = isP ? g_P : g_Q;

    if (blockIdx.z == 0 && blockIdx.y == 0 && blockIdx.x < 64) {
        int idx = blockIdx.x * 256 + t;
        g_rowsum[idx] = 0.0f;
        g_colsum[idx] = 0.0f;
    }

    #pragma unroll 8
    for (int it = 0; it < 32; it++) {
        int c = w + it * 8;
        tile[lane][c] = src[((size_t)b * CDIM + c) * NSP + m0 + lane];
    }
    __syncthreads();

    #pragma unroll
    for (int r = 0; r < 4; r++) {
        int row = w * 4 + r;
        float s = 0.0f;
        #pragma unroll
        for (int k = 0; k < 8; k++) {
            float v = tile[row][lane + 32 * k];
            s = fmaf(v, v, s);
        }
        #pragma unroll
        for (int off = 16; off > 0; off >>= 1)
            s += __shfl_down_sync(0xFFFFFFFFu, s, off);
        float invn = 1.0f / fmaxf(sqrtf(__shfl_sync(0xFFFFFFFFu, s, 0)), 1e-12f);

        size_t obase = ((size_t)b * NSP + m0 + row) * KTOT;
        #pragma unroll
        for (int k = 0; k < 8; k++) {
            int c = lane + 32 * k;
            float v = tile[row][c] * invn;
            __nv_bfloat16 hi = __float2bfloat16(v);
            __nv_bfloat16 lo = __float2bfloat16(v - __bfloat162float(hi));
            dst[obase + c] = hi;
            dst[obase + 256 + c] = isP ? lo : hi;
            dst[obase + 512 + c] = isP ? hi : lo;
        }
    }
}

// ---------------------------------------------------------------------------
// Kernel 2: HMMA GEMM (128x128, K=768, 2 CTA/SM, double buffer) [R10 config]
// + exp epilogue -> g_E; accumulates row/col sums.
// ---------------------------------------------------------------------------
#define SMEM_BUFS  1024
#define SMEM_TOTAL (1024 + 4 * 16384)

__global__ __launch_bounds__(256, 2)
void gemm_exp_kernel(const float* __restrict__ alpha_p) {
    extern __shared__ char smem[];
    const uint32_t sbase = smem_u32(smem);
    float* srow = (float*)smem;
    float* scol = (float*)(smem + 512);

    const int t = threadIdx.x;
    const int w = t >> 5, lane = t & 31;
    const int b  = blockIdx.z;
    const int i0 = blockIdx.y * 128;
    const int j0 = blockIdx.x * 128;

    if (t < 128) { srow[t] = 0.0f; scol[t] = 0.0f; }

    const __nv_bfloat16* Abase = g_P + ((size_t)b * NSP + i0) * KTOT;
    const __nv_bfloat16* Bbase = g_Q + ((size_t)b * NSP + j0) * KTOT;

    auto load_chunk = [&](int c, int buf) {
        uint32_t aS = sbase + SMEM_BUFS + buf * 32768;
        uint32_t bS = aS + 16384;
        #pragma unroll
        for (int u = 0; u < 4; u++) {
            int f = t + 256 * u;
            uint32_t row = f >> 3, seg = f & 7;
            uint32_t off = row * 128 + ((seg ^ (row & 7)) << 4);
            cp16(aS + off, Abase + (size_t)row * KTOT + c * 64 + seg * 8);
            cp16(bS + off, Bbase + (size_t)row * KTOT + c * 64 + seg * 8);
        }
    };

    const int wm = w >> 2, wn = w & 3;
    const int r16 = lane & 15, ahi = lane >> 4;
    const int bn  = (lane & 7) + ((lane >> 4) << 3);
    const int bkl = (lane >> 3) & 1;

    float d[4][4][4] = {};

    load_chunk(0, 0);
    cp_commit();

    #pragma unroll 1
    for (int c = 0; c < NCHUNK; c++) {
        if (c < NCHUNK - 1) { load_chunk(c + 1, (c + 1) & 1); cp_commit(); }
        if (c < NCHUNK - 1) cp_wait<1>(); else cp_wait<0>();
        __syncthreads();

        uint32_t aS = sbase + SMEM_BUFS + (c & 1) * 32768;
        uint32_t bS = aS + 16384;

        #pragma unroll
        for (int kk = 0; kk < 4; kk++) {
            uint32_t afr[4][4];
            #pragma unroll
            for (int mt = 0; mt < 4; mt++) {
                uint32_t row = wm * 64 + mt * 16 + r16;
                uint32_t col = (((2 * kk + ahi) ^ (r16 & 7)) << 4);
                ldmx4(afr[mt], aS + row * 128 + col);
            }
            uint32_t bfr[4][2];
            #pragma unroll
            for (int np = 0; np < 2; np++) {
                uint32_t nrow = wn * 32 + np * 16 + bn;
                uint32_t col = (((2 * kk + bkl) ^ (bn & 7)) << 4);
                uint32_t q[4];
                ldmx4(q, bS + nrow * 128 + col);
                bfr[2 * np][0] = q[0]; bfr[2 * np][1] = q[1];
                bfr[2 * np + 1][0] = q[2]; bfr[2 * np + 1][1] = q[3];
            }
            #pragma unroll
            for (int mt = 0; mt < 4; mt++)
                #pragma unroll
                for (int nt = 0; nt < 4; nt++)
                    mma16816(d[mt][nt], afr[mt], bfr[nt]);
        }
        __syncthreads();
    }

    const float alpha = __ldg(alpha_p);
    const int g = lane >> 2, tg = lane & 3;
    float csum[4][2] = {};
    float* outb = g_E + (size_t)b * BN2;

    #pragma unroll
    for (int mt = 0; mt < 4; mt++) {
        float rs0 = 0.0f, rs1 = 0.0f;
        const int row0 = i0 + wm * 64 + mt * 16 + g;
        #pragma unroll
        for (int nt = 0; nt < 4; nt++) {
            float e0 = __expf(d[mt][nt][0] * alpha);
            float e1 = __expf(d[mt][nt][1] * alpha);
            float e2 = __expf(d[mt][nt][2] * alpha);
            float e3 = __expf(d[mt][nt][3] * alpha);
            rs0 += e0 + e1; rs1 += e2 + e3;
            csum[nt][0] += e0 + e2; csum[nt][1] += e1 + e3;
            const int colg = j0 + wn * 32 + nt * 8 + tg * 2;
            *(float2*)(outb + (size_t)row0 * NSP + colg)       = make_float2(e0, e1);
            *(float2*)(outb + (size_t)(row0 + 8) * NSP + colg) = make_float2(e2, e3);
        }
        rs0 += __shfl_xor_sync(0xFFFFFFFFu, rs0, 1);
        rs0 += __shfl_xor_sync(0xFFFFFFFFu, rs0, 2);
        rs1 += __shfl_xor_sync(0xFFFFFFFFu, rs1, 1);
        rs1 += __shfl_xor_sync(0xFFFFFFFFu, rs1, 2);
        if (tg == 0) {
            atomicAdd(&srow[wm * 64 + mt * 16 + g],     rs0);
            atomicAdd(&srow[wm * 64 + mt * 16 + g + 8], rs1);
        }
    }
    #pragma unroll
    for (int nt = 0; nt < 4; nt++)
        #pragma unroll
        for (int cc = 0; cc < 2; cc++) {
            float v = csum[nt][cc];
            v += __shfl_xor_sync(0xFFFFFFFFu, v, 4);
            v += __shfl_xor_sync(0xFFFFFFFFu, v, 8);
            v += __shfl_xor_sync(0xFFFFFFFFu, v, 16);
            if (g == 0) atomicAdd(&scol[wn * 32 + nt * 8 + tg * 2 + cc], v);
        }
    __syncthreads();
    if (t < 128) {
        atomicAdd(&g_rowsum[b * NSP + i0 + t], srow[t]);
        atomicAdd(&g_colsum[b * NSP + j0 + t], scol[t]);
    }
}

// ---------------------------------------------------------------------------
// Kernel 2b: inverse sums (tiny)
// ---------------------------------------------------------------------------
__global__ void inv_kernel() {
    int i = blockIdx.x * 256 + threadIdx.x;
    g_invr[i] = 1.0f / g_rowsum[i];
    g_invc[i] = 1.0f / g_colsum[i];
}

// ---------------------------------------------------------------------------
// top-3 helpers
// ---------------------------------------------------------------------------
__device__ __forceinline__ void top3_push(float v, float& v0, float& v1, float& v2) {
    if (v > v2) {
        if (v > v1) {
            v2 = v1;
            if (v > v0) { v1 = v0; v0 = v; } else { v1 = v; }
        } else v2 = v;
    }
}
__device__ __forceinline__ void warp_reduce_top3(float& v0, float& v1, float& v2) {
    #pragma unroll
    for (int off = 16; off > 0; off >>= 1) {
        float u0 = __shfl_down_sync(0xFFFFFFFFu, v0, off);
        float u1 = __shfl_down_sync(0xFFFFFFFFu, v1, off);
        float u2 = __shfl_down_sync(0xFFFFFFFFu, v2, off);
        top3_push(u0, v0, v1, v2);
        top3_push(u1, v0, v1, v2);
        top3_push(u2, v0, v1, v2);
    }
}

// ---------------------------------------------------------------------------
// Kernel 3: finish — interleaved roles [R10 body], REVERSE batch order so
// the first finish wave reads the g_E region gemm wrote LAST (L2-resident).
// ---------------------------------------------------------------------------
__global__ __launch_bounds__(256)
void finish_kernel(float* __restrict__ xcq, float* __restrict__ xcp,
                   float* __restrict__ valp) {
    __shared__ float tile[2][128][17];
    const int b  = (BATCH - 1) - blockIdx.y;   // reverse batch order
    const int bx = blockIdx.x;
    const int t  = threadIdx.x;
    const int w  = t >> 5, lane = t & 31;

    if (bx % 3 == 0) {
        // ---------------- row role (reverse row order within batch) --------
        const int ri = 511 - bx / 3;
        const int i  = ri * 8 + w;
        const float invr = g_invr[b * NSP + i];
        const float* invc = g_invc + b * NSP;
        const float* src = g_E + (size_t)b * BN2 + (size_t)i * NSP;
        float*       dst = xcq + (size_t)b * BN2 + (size_t)i * NSP;

        float v0 = -1e30f, v1 = -1e30f, v2 = -1e30f;
        for (int jb = lane * 4; jb < NSP; jb += 128) {
            float4 e  = *(const float4*)(src + jb);
            float4 ic = *(const float4*)(invc + jb);
            float x0 = e.x * e.x * invr * ic.x;
            float x1 = e.y * e.y * invr * ic.y;
            float x2 = e.z * e.z * invr * ic.z;
            float x3 = e.w * e.w * invr * ic.w;
            *(float4*)(dst + jb) = make_float4(x0, x1, x2, x3);
            top3_push(x0, v0, v1, v2);
            top3_push(x1, v0, v1, v2);
            top3_push(x2, v0, v1, v2);
            top3_push(x3, v0, v1, v2);
        }
        warp_reduce_top3(v0, v1, v2);
        if (lane == 0) {
            valp[b * 3 * NSP + 0 * NSP + i] = v0;
            valp[b * 3 * NSP + 1 * NSP + i] = v1;
            valp[b * 3 * NSP + 2 * NSP + i] = v2;
        }
    } else {
        // ---------------- col role (reverse quarter order) ----------------
        const int ci = bx - 1 - bx / 3;          // 0..1023
        const int j0 = (ci & 255) * 16;
        const int ry = 3 - (ci >> 8);            // reverse row-quarter
        const int i0 = ry * 1024;
        const int lrow = t >> 4, lcol = t & 15;
        const float invc_l = g_invc[b * NSP + j0 + lcol];
        const float* invr = g_invr + b * NSP;
        const float* src = g_E + (size_t)b * BN2;
        float*       dst = xcp + (size_t)b * BN2;

        float c0[2], c1[2], c2[2];
        #pragma unroll
        for (int k = 0; k < 2; k++) { c0[k] = -1e30f; c1[k] = -1e30f; c2[k] = -1e30f; }

        auto load = [&](int ic, int bf) {
            #pragma unroll
            for (int u = 0; u < 8; u++) {
                int r = lrow + u * 16;
                float e = src[(size_t)(ic + r) * NSP + j0 + lcol];
                tile[bf][r][lcol] = e * e * invr[ic + r] * invc_l;
            }
        };

        // walk rows in reverse within the quarter (gemm wrote high rows last)
        load(i0 + 1024 - 128, 0);
        int bf = 0;

        #pragma unroll 1
        for (int ic = i0 + 1024 - 128; ic >= i0; ic -= 128) {
            __syncthreads();
            if (ic - 128 >= i0) load(ic - 128, bf ^ 1);

            #pragma unroll
            for (int cc = 0; cc < 2; cc++) {
                const int col = w * 2 + cc;
                #pragma unroll
                for (int g2 = 0; g2 < 4; g2++) {
                    float v = tile[bf][g2 * 32 + lane][col];
                    dst[(size_t)(j0 + col) * NSP + ic + g2 * 32 + lane] = v;
                    top3_push(v, c0[cc], c1[cc], c2[cc]);
                }
            }
            bf ^= 1;
        }

        #pragma unroll
        for (int cc = 0; cc < 2; cc++) {
            float v0 = c0[cc], v1 = c1[cc], v2 = c2[cc];
            warp_reduce_top3(v0, v1, v2);
            if (lane == 0) {
                const int base = (b * 4 + ry) * 3;
                const int j = j0 + w * 2 + cc;
                g_cpart[(base + 0) * NSP + j] = v0;
                g_cpart[(base + 1) * NSP + j] = v1;
                g_cpart[(base + 2) * NSP + j] = v2;
            }
        }
    }
}

// ---------------------------------------------------------------------------
// Kernel 4: merge 4 column partials -> valq
// ---------------------------------------------------------------------------
__global__ __launch_bounds__(256)
void valq_reduce_kernel(float* __restrict__ valq) {
    const int b = blockIdx.y;
    const int j = blockIdx.x * 256 + threadIdx.x;
    float v0 = -1e30f, v1 = -1e30f, v2 = -1e30f;
    #pragma unroll
    for (int p = 0; p < 4; p++) {
        const int base = (b * 4 + p) * 3;
        top3_push(g_cpart[(base + 0) * NSP + j], v0, v1, v2);
        top3_push(g_cpart[(base + 1) * NSP + j], v0, v1, v2);
        top3_push(g_cpart[(base + 2) * NSP + j], v0, v1, v2);
    }
    valq[b * 3 * NSP + 0 * NSP + j] = v0;
    valq[b * 3 * NSP + 1 * NSP + j] = v1;
    valq[b * 3 * NSP + 2 * NSP + j] = v2;
}

// ---------------------------------------------------------------------------
extern "C" void kernel_launch(void* const* d_in, const int* in_sizes, int n_in,
                              void* d_out, int out_size) {
    const float* xp    = (const float*)d_in[0];
    const float* xq    = (const float*)d_in[1];
    const float* alpha = (const float*)d_in[2];

    float* valp = (float*)d_out;
    float* valq = valp + BATCH * 3 * NSP;
    float* xcp  = valq + BATCH * 3 * NSP;
    float* xcq  = xcp + (size_t)BATCH * BN2;

    cudaFuncSetAttribute(gemm_exp_kernel,
                         cudaFuncAttributeMaxDynamicSharedMemorySize, SMEM_TOTAL);

    prep_kernel<<<dim3(128, BATCH, 2), 256>>>(xp, xq);
    gemm_exp_kernel<<<dim3(32, 32, BATCH), 256, SMEM_TOTAL>>>(alpha);
    inv_kernel<<<64, 256>>>();
    finish_kernel<<<dim3(1536, BATCH), 256>>>(xcq, xcp, valp);
    valq_reduce_kernel<<<dim3(16, BATCH), 256>>>(valq);
}

// round 16
// speedup vs baseline: 1.7750x; 1.0093x over previous
#include <cuda_runtime.h>
#include <cuda_bf16.h>
#include <math.h>
#include <cstdint>

#define BATCH 4
#define CDIM  256
#define NSP   4096
#define BN2   16777216
#define KTOT  768          // [hi | lo | hi] x [hi | hi | lo]
#define NCHUNK 12          // K chunks of 64

// ---------------------------------------------------------------------------
// Device scratch
// ---------------------------------------------------------------------------
__device__ float g_rowsum[BATCH * NSP];
__device__ float g_colsum[BATCH * NSP];
__device__ float g_invr[BATCH * NSP];
__device__ float g_invc[BATCH * NSP];
__device__ __nv_bfloat16 g_P[(size_t)BATCH * NSP * KTOT];
__device__ __nv_bfloat16 g_Q[(size_t)BATCH * NSP * KTOT];
__device__ float g_E[(size_t)BATCH * BN2];       // e = exp(alpha*dot)
__device__ float g_cpart[BATCH * 8 * 3 * NSP];   // [b][octant][3][col]

// ---------------------------------------------------------------------------
// PTX helpers (sm_80-compatible: cp.async, ldmatrix, mma.sync)
// ---------------------------------------------------------------------------
__device__ __forceinline__ uint32_t smem_u32(const void* p) {
    uint32_t a;
    asm("{ .reg .u64 t; cvta.to.shared.u64 t, %1; cvt.u32.u64 %0, t; }"
        : "=r"(a) : "l"(p));
    return a;
}
__device__ __forceinline__ void cp16(uint32_t s, const void* g) {
    asm volatile("cp.async.cg.shared.global [%0], [%1], 16;" :: "r"(s), "l"(g));
}
__device__ __forceinline__ void cp_commit() {
    asm volatile("cp.async.commit_group;");
}
template <int N>
__device__ __forceinline__ void cp_wait() {
    asm volatile("cp.async.wait_group %0;" :: "n"(N));
}
__device__ __forceinline__ void ldmx4(uint32_t* r, uint32_t addr) {
    asm volatile("ldmatrix.sync.aligned.m8n8.x4.shared.b16 {%0,%1,%2,%3}, [%4];"
                 : "=r"(r[0]), "=r"(r[1]), "=r"(r[2]), "=r"(r[3]) : "r"(addr));
}
__device__ __forceinline__ void mma16816(float* d, const uint32_t* a, const uint32_t* b) {
    asm volatile(
        "mma.sync.aligned.m16n8k16.row.col.f32.bf16.bf16.f32 "
        "{%0,%1,%2,%3}, {%4,%5,%6,%7}, {%8,%9}, {%0,%1,%2,%3};"
        : "+f"(d[0]), "+f"(d[1]), "+f"(d[2]), "+f"(d[3])
        : "r"(a[0]), "r"(a[1]), "r"(a[2]), "r"(a[3]), "r"(b[0]), "r"(b[1]));
}

// ---------------------------------------------------------------------------
// Kernel 1: prep — L2-normalize over channels, bf16 hi/lo split, K-major
// [m][768]. Also zeroes the sum accumulators.
// ---------------------------------------------------------------------------
__global__ __launch_bounds__(256)
void prep_kernel(const float* __restrict__ xp, const float* __restrict__ xq) {
    __shared__ float tile[32][257];
    const int m0 = blockIdx.x * 32;
    const int b  = blockIdx.y;
    const int t  = threadIdx.x;
    const int w  = t >> 5, lane = t & 31;
    const bool isP = (blockIdx.z == 0);
    const float* src = isP ? xp : xq;
    __nv_bfloat16* dst = isP ? g_P : g_Q;

    if (blockIdx.z == 0 && blockIdx.y == 0 && blockIdx.x < 64) {
        int idx = blockIdx.x * 256 + t;
        g_rowsum[idx] = 0.0f;
        g_colsum[idx] = 0.0f;
    }

    #pragma unroll 8
    for (int it = 0; it < 32; it++) {
        int c = w + it * 8;
        tile[lane][c] = src[((size_t)b * CDIM + c) * NSP + m0 + lane];
    }
    __syncthreads();

    #pragma unroll
    for (int r = 0; r < 4; r++) {
        int row = w * 4 + r;
        float s = 0.0f;
        #pragma unroll
        for (int k = 0; k < 8; k++) {
            float v = tile[row][lane + 32 * k];
            s = fmaf(v, v, s);
        }
        #pragma unroll
        for (int off = 16; off > 0; off >>= 1)
            s += __shfl_down_sync(0xFFFFFFFFu, s, off);
        float invn = 1.0f / fmaxf(sqrtf(__shfl_sync(0xFFFFFFFFu, s, 0)), 1e-12f);

        size_t obase = ((size_t)b * NSP + m0 + row) * KTOT;
        #pragma unroll
        for (int k = 0; k < 8; k++) {
            int c = lane + 32 * k;
            float v = tile[row][c] * invn;
            __nv_bfloat16 hi = __float2bfloat16(v);
            __nv_bfloat16 lo = __float2bfloat16(v - __bfloat162float(hi));
            dst[obase + c] = hi;
            dst[obase + 256 + c] = isP ? lo : hi;
            dst[obase + 512 + c] = isP ? hi : lo;
        }
    }
}

// ---------------------------------------------------------------------------
// Kernel 2: HMMA GEMM (128x128, K=768, 2 CTA/SM, double buffer) [R10 config]
// + exp epilogue -> g_E; accumulates row/col sums.
// ---------------------------------------------------------------------------
#define SMEM_BUFS  1024
#define SMEM_TOTAL (1024 + 4 * 16384)

__global__ __launch_bounds__(256, 2)
void gemm_exp_kernel(const float* __restrict__ alpha_p) {
    extern __shared__ char smem[];
    const uint32_t sbase = smem_u32(smem);
    float* srow = (float*)smem;
    float* scol = (float*)(smem + 512);

    const int t = threadIdx.x;
    const int w = t >> 5, lane = t & 31;
    const int b  = blockIdx.z;
    const int i0 = blockIdx.y * 128;
    const int j0 = blockIdx.x * 128;

    if (t < 128) { srow[t] = 0.0f; scol[t] = 0.0f; }

    const __nv_bfloat16* Abase = g_P + ((size_t)b * NSP + i0) * KTOT;
    const __nv_bfloat16* Bbase = g_Q + ((size_t)b * NSP + j0) * KTOT;

    auto load_chunk = [&](int c, int buf) {
        uint32_t aS = sbase + SMEM_BUFS + buf * 32768;
        uint32_t bS = aS + 16384;
        #pragma unroll
        for (int u = 0; u < 4; u++) {
            int f = t + 256 * u;
            uint32_t row = f >> 3, seg = f & 7;
            uint32_t off = row * 128 + ((seg ^ (row & 7)) << 4);
            cp16(aS + off, Abase + (size_t)row * KTOT + c * 64 + seg * 8);
            cp16(bS + off, Bbase + (size_t)row * KTOT + c * 64 + seg * 8);
        }
    };

    const int wm = w >> 2, wn = w & 3;
    const int r16 = lane & 15, ahi = lane >> 4;
    const int bn  = (lane & 7) + ((lane >> 4) << 3);
    const int bkl = (lane >> 3) & 1;

    float d[4][4][4] = {};

    load_chunk(0, 0);
    cp_commit();

    #pragma unroll 1
    for (int c = 0; c < NCHUNK; c++) {
        if (c < NCHUNK - 1) { load_chunk(c + 1, (c + 1) & 1); cp_commit(); }
        if (c < NCHUNK - 1) cp_wait<1>(); else cp_wait<0>();
        __syncthreads();

        uint32_t aS = sbase + SMEM_BUFS + (c & 1) * 32768;
        uint32_t bS = aS + 16384;

        #pragma unroll
        for (int kk = 0; kk < 4; kk++) {
            uint32_t afr[4][4];
            #pragma unroll
            for (int mt = 0; mt < 4; mt++) {
                uint32_t row = wm * 64 + mt * 16 + r16;
                uint32_t col = (((2 * kk + ahi) ^ (r16 & 7)) << 4);
                ldmx4(afr[mt], aS + row * 128 + col);
            }
            uint32_t bfr[4][2];
            #pragma unroll
            for (int np = 0; np < 2; np++) {
                uint32_t nrow = wn * 32 + np * 16 + bn;
                uint32_t col = (((2 * kk + bkl) ^ (bn & 7)) << 4);
                uint32_t q[4];
                ldmx4(q, bS + nrow * 128 + col);
                bfr[2 * np][0] = q[0]; bfr[2 * np][1] = q[1];
                bfr[2 * np + 1][0] = q[2]; bfr[2 * np + 1][1] = q[3];
            }
            #pragma unroll
            for (int mt = 0; mt < 4; mt++)
                #pragma unroll
                for (int nt = 0; nt < 4; nt++)
                    mma16816(d[mt][nt], afr[mt], bfr[nt]);
        }
        __syncthreads();
    }

    const float alpha = __ldg(alpha_p);
    const int g = lane >> 2, tg = lane & 3;
    float csum[4][2] = {};
    float* outb = g_E + (size_t)b * BN2;

    #pragma unroll
    for (int mt = 0; mt < 4; mt++) {
        float rs0 = 0.0f, rs1 = 0.0f;
        const int row0 = i0 + wm * 64 + mt * 16 + g;
        #pragma unroll
        for (int nt = 0; nt < 4; nt++) {
            float e0 = __expf(d[mt][nt][0] * alpha);
            float e1 = __expf(d[mt][nt][1] * alpha);
            float e2 = __expf(d[mt][nt][2] * alpha);
            float e3 = __expf(d[mt][nt][3] * alpha);
            rs0 += e0 + e1; rs1 += e2 + e3;
            csum[nt][0] += e0 + e2; csum[nt][1] += e1 + e3;
            const int colg = j0 + wn * 32 + nt * 8 + tg * 2;
            *(float2*)(outb + (size_t)row0 * NSP + colg)       = make_float2(e0, e1);
            *(float2*)(outb + (size_t)(row0 + 8) * NSP + colg) = make_float2(e2, e3);
        }
        rs0 += __shfl_xor_sync(0xFFFFFFFFu, rs0, 1);
        rs0 += __shfl_xor_sync(0xFFFFFFFFu, rs0, 2);
        rs1 += __shfl_xor_sync(0xFFFFFFFFu, rs1, 1);
        rs1 += __shfl_xor_sync(0xFFFFFFFFu, rs1, 2);
        if (tg == 0) {
            atomicAdd(&srow[wm * 64 + mt * 16 + g],     rs0);
            atomicAdd(&srow[wm * 64 + mt * 16 + g + 8], rs1);
        }
    }
    #pragma unroll
    for (int nt = 0; nt < 4; nt++)
        #pragma unroll
        for (int cc = 0; cc < 2; cc++) {
            float v = csum[nt][cc];
            v += __shfl_xor_sync(0xFFFFFFFFu, v, 4);
            v += __shfl_xor_sync(0xFFFFFFFFu, v, 8);
            v += __shfl_xor_sync(0xFFFFFFFFu, v, 16);
            if (g == 0) atomicAdd(&scol[wn * 32 + nt * 8 + tg * 2 + cc], v);
        }
    __syncthreads();
    if (t < 128) {
        atomicAdd(&g_rowsum[b * NSP + i0 + t], srow[t]);
        atomicAdd(&g_colsum[b * NSP + j0 + t], scol[t]);
    }
}

// ---------------------------------------------------------------------------
// Kernel 2b: inverse sums (tiny)
// ---------------------------------------------------------------------------
__global__ void inv_kernel() {
    int i = blockIdx.x * 256 + threadIdx.x;
    g_invr[i] = 1.0f / g_rowsum[i];
    g_invc[i] = 1.0f / g_colsum[i];
}

// ---------------------------------------------------------------------------
// top-3 helpers
// ---------------------------------------------------------------------------
__device__ __forceinline__ void top3_push(float v, float& v0, float& v1, float& v2) {
    if (v > v2) {
        if (v > v1) {
            v2 = v1;
            if (v > v0) { v1 = v0; v0 = v; } else { v1 = v; }
        } else v2 = v;
    }
}
__device__ __forceinline__ void warp_reduce_top3(float& v0, float& v1, float& v2) {
    #pragma unroll
    for (int off = 16; off > 0; off >>= 1) {
        float u0 = __shfl_down_sync(0xFFFFFFFFu, v0, off);
        float u1 = __shfl_down_sync(0xFFFFFFFFu, v1, off);
        float u2 = __shfl_down_sync(0xFFFFFFFFu, v2, off);
        top3_push(u0, v0, v1, v2);
        top3_push(u1, v0, v1, v2);
        top3_push(u2, v0, v1, v2);
    }
}

// ---------------------------------------------------------------------------
// Kernel 3: finish — interleaved roles, reverse order (L2 residue).
// Row role unchanged. Col role v2: 32-col strips x 512-row octants with
// float4 128B-segment loads; smem [64][33] (scalar STS, conflict-free both
// phases); 128B coalesced column writes; octant top-3 partials.
// ---------------------------------------------------------------------------
__global__ __launch_bounds__(256)
void finish_kernel(float* __restrict__ xcq, float* __restrict__ xcp,
                   float* __restrict__ valp) {
    __shared__ float tile[2][64][33];     // 17.4 KB
    const int b  = (BATCH - 1) - blockIdx.y;   // reverse batch order
    const int bx = blockIdx.x;
    const int t  = threadIdx.x;
    const int w  = t >> 5, lane = t & 31;

    if (bx % 3 == 0) {
        // ---------------- row role (reverse row order) ----------------
        const int ri = 511 - bx / 3;
        const int i  = ri * 8 + w;
        const float invr = g_invr[b * NSP + i];
        const float* invc = g_invc + b * NSP;
        const float* src = g_E + (size_t)b * BN2 + (size_t)i * NSP;
        float*       dst = xcq + (size_t)b * BN2 + (size_t)i * NSP;

        float v0 = -1e30f, v1 = -1e30f, v2 = -1e30f;
        for (int jb = lane * 4; jb < NSP; jb += 128) {
            float4 e  = *(const float4*)(src + jb);
            float4 ic = *(const float4*)(invc + jb);
            float x0 = e.x * e.x * invr * ic.x;
            float x1 = e.y * e.y * invr * ic.y;
            float x2 = e.z * e.z * invr * ic.z;
            float x3 = e.w * e.w * invr * ic.w;
            *(float4*)(dst + jb) = make_float4(x0, x1, x2, x3);
            top3_push(x0, v0, v1, v2);
            top3_push(x1, v0, v1, v2);
            top3_push(x2, v0, v1, v2);
            top3_push(x3, v0, v1, v2);
        }
        warp_reduce_top3(v0, v1, v2);
        if (lane == 0) {
            valp[b * 3 * NSP + 0 * NSP + i] = v0;
            valp[b * 3 * NSP + 1 * NSP + i] = v1;
            valp[b * 3 * NSP + 2 * NSP + i] = v2;
        }
    } else {
        // ------------- col role: 32-col strip x 512-row octant -------------
        const int ci  = bx - 1 - bx / 3;          // 0..1023
        const int j0  = (ci & 127) * 32;
        const int oct = 7 - (ci >> 7);            // reverse octant order
        const int i0  = oct * 512;
        const int lr  = t >> 3;                   // 0..31
        const int lc4 = (t & 7) * 4;              // 0,4,...,28
        const float4 ic4 = *(const float4*)(g_invc + b * NSP + j0 + lc4);
        const float* invr = g_invr + b * NSP;
        const float* src = g_E + (size_t)b * BN2;
        float*       dst = xcp + (size_t)b * BN2;

        float c0[4], c1[4], c2[4];
        #pragma unroll
        for (int k = 0; k < 4; k++) { c0[k] = -1e30f; c1[k] = -1e30f; c2[k] = -1e30f; }

        // load 64 rows (descending blocks) into buffer bf: x = e^2*invr*invc
        auto load = [&](int ic, int bf) {
            #pragma unroll
            for (int u = 0; u < 2; u++) {
                const int r = lr + u * 32;
                float4 e = *(const float4*)(src + (size_t)(ic + r) * NSP + j0 + lc4);
                const float ir = invr[ic + r];
                float* tp = &tile[bf][r][lc4];
                tp[0] = e.x * e.x * ir * ic4.x;
                tp[1] = e.y * e.y * ir * ic4.y;
                tp[2] = e.z * e.z * ir * ic4.z;
                tp[3] = e.w * e.w * ir * ic4.w;
            }
        };

        load(i0 + 512 - 64, 0);
        int bf = 0;

        #pragma unroll 1
        for (int ic = i0 + 512 - 64; ic >= i0; ic -= 64) {
            __syncthreads();
            if (ic - 64 >= i0) load(ic - 64, bf ^ 1);

            // warp w owns cols 4w..4w+3; 128B coalesced column writes
            #pragma unroll
            for (int cc = 0; cc < 4; cc++) {
                const int col = w * 4 + cc;
                #pragma unroll
                for (int g2 = 0; g2 < 2; g2++) {
                    float v = tile[bf][g2 * 32 + lane][col];
                    dst[(size_t)(j0 + col) * NSP + ic + g2 * 32 + lane] = v;
                    top3_push(v, c0[cc], c1[cc], c2[cc]);
                }
            }
            bf ^= 1;
        }

        #pragma unroll
        for (int cc = 0; cc < 4; cc++) {
            float v0 = c0[cc], v1 = c1[cc], v2 = c2[cc];
            warp_reduce_top3(v0, v1, v2);
            if (lane == 0) {
                const int base = (b * 8 + oct) * 3;
                const int j = j0 + w * 4 + cc;
                g_cpart[(base + 0) * NSP + j] = v0;
                g_cpart[(base + 1) * NSP + j] = v1;
                g_cpart[(base + 2) * NSP + j] = v2;
            }
        }
    }
}

// ---------------------------------------------------------------------------
// Kernel 4: merge 8 column partials -> valq
// ---------------------------------------------------------------------------
__global__ __launch_bounds__(256)
void valq_reduce_kernel(float* __restrict__ valq) {
    const int b = blockIdx.y;
    const int j = blockIdx.x * 256 + threadIdx.x;
    float v0 = -1e30f, v1 = -1e30f, v2 = -1e30f;
    #pragma unroll
    for (int p = 0; p < 8; p++) {
        const int base = (b * 8 + p) * 3;
        top3_push(g_cpart[(base + 0) * NSP + j], v0, v1, v2);
        top3_push(g_cpart[(base + 1) * NSP + j], v0, v1, v2);
        top3_push(g_cpart[(base + 2) * NSP + j], v0, v1, v2);
    }
    valq[b * 3 * NSP + 0 * NSP + j] = v0;
    valq[b * 3 * NSP + 1 * NSP + j] = v1;
    valq[b * 3 * NSP + 2 * NSP + j] = v2;
}

// ---------------------------------------------------------------------------
extern "C" void kernel_launch(void* const* d_in, const int* in_sizes, int n_in,
                              void* d_out, int out_size) {
    const float* xp    = (const float*)d_in[0];
    const float* xq    = (const float*)d_in[1];
    const float* alpha = (const float*)d_in[2];

    float* valp = (float*)d_out;
    float* valq = valp + BATCH * 3 * NSP;
    float* xcp  = valq + BATCH * 3 * NSP;
    float* xcq  = xcp + (size_t)BATCH * BN2;

    cudaFuncSetAttribute(gemm_exp_kernel,
                         cudaFuncAttributeMaxDynamicSharedMemorySize, SMEM_TOTAL);

    prep_kernel<<<dim3(128, BATCH, 2), 256>>>(xp, xq);
    gemm_exp_kernel<<<dim3(32, 32, BATCH), 256, SMEM_TOTAL>>>(alpha);
    inv_kernel<<<64, 256>>>();
    finish_kernel<<<dim3(1536, BATCH), 256>>>(xcq, xcp, valp);
    valq_reduce_kernel<<<dim3(16, BATCH), 256>>>(valq);
}

// round 17
// speedup vs baseline: 1.7944x; 1.0109x over previous
#include <cuda_runtime.h>
#include <cuda_bf16.h>
#include <math.h>
#include <cstdint>

#define BATCH 4
#define CDIM  256
#define NSP   4096
#define BN2   16777216
#define KTOT  768          // [hi | lo | hi] x [hi | hi | lo]
#define NCHUNK 12          // K chunks of 64

// ---------------------------------------------------------------------------
// Device scratch
// ---------------------------------------------------------------------------
__device__ float g_rowsum[BATCH * NSP];
__device__ float g_colsum[BATCH * NSP];
__device__ float g_invr[BATCH * NSP];
__device__ float g_invc[BATCH * NSP];
__device__ __nv_bfloat16 g_P[(size_t)BATCH * NSP * KTOT];
__device__ __nv_bfloat16 g_Q[(size_t)BATCH * NSP * KTOT];
__device__ float g_E[(size_t)BATCH * BN2];       // e = exp(alpha*dot)
__device__ float g_cpart[BATCH * 8 * 3 * NSP];   // [b][octant][3][col]

// ---------------------------------------------------------------------------
// PTX helpers (sm_80-compatible: cp.async, ldmatrix, mma.sync)
// ---------------------------------------------------------------------------
__device__ __forceinline__ uint32_t smem_u32(const void* p) {
    uint32_t a;
    asm("{ .reg .u64 t; cvta.to.shared.u64 t, %1; cvt.u32.u64 %0, t; }"
        : "=r"(a) : "l"(p));
    return a;
}
__device__ __forceinline__ void cp16(uint32_t s, const void* g) {
    asm volatile("cp.async.cg.shared.global [%0], [%1], 16;" :: "r"(s), "l"(g));
}
__device__ __forceinline__ void cp_commit() {
    asm volatile("cp.async.commit_group;");
}
template <int N>
__device__ __forceinline__ void cp_wait() {
    asm volatile("cp.async.wait_group %0;" :: "n"(N));
}
__device__ __forceinline__ void ldmx4(uint32_t* r, uint32_t addr) {
    asm volatile("ldmatrix.sync.aligned.m8n8.x4.shared.b16 {%0,%1,%2,%3}, [%4];"
                 : "=r"(r[0]), "=r"(r[1]), "=r"(r[2]), "=r"(r[3]) : "r"(addr));
}
__device__ __forceinline__ void mma16816(float* d, const uint32_t* a, const uint32_t* b) {
    asm volatile(
        "mma.sync.aligned.m16n8k16.row.col.f32.bf16.bf16.f32 "
        "{%0,%1,%2,%3}, {%4,%5,%6,%7}, {%8,%9}, {%0,%1,%2,%3};"
        : "+f"(d[0]), "+f"(d[1]), "+f"(d[2]), "+f"(d[3])
        : "r"(a[0]), "r"(a[1]), "r"(a[2]), "r"(a[3]), "r"(b[0]), "r"(b[1]));
}

// ---------------------------------------------------------------------------
// Kernel 1: prep — L2-normalize over channels, bf16 hi/lo split, K-major
// [m][768]. Also zeroes the sum accumulators.
// ---------------------------------------------------------------------------
__global__ __launch_bounds__(256)
void prep_kernel(const float* __restrict__ xp, const float* __restrict__ xq) {
    __shared__ float tile[32][257];
    const int m0 = blockIdx.x * 32;
    const int b  = blockIdx.y;
    const int t  = threadIdx.x;
    const int w  = t >> 5, lane = t & 31;
    const bool isP = (blockIdx.z == 0);
    const float* src = isP ? xp : xq;
    __nv_bfloat16* dst = isP ? g_P : g_Q;

    if (blockIdx.z == 0 && blockIdx.y == 0 && blockIdx.x < 64) {
        int idx = blockIdx.x * 256 + t;
        g_rowsum[idx] = 0.0f;
        g_colsum[idx] = 0.0f;
    }

    #pragma unroll 8
    for (int it = 0; it < 32; it++) {
        int c = w + it * 8;
        tile[lane][c] = src[((size_t)b * CDIM + c) * NSP + m0 + lane];
    }
    __syncthreads();

    #pragma unroll
    for (int r = 0; r < 4; r++) {
        int row = w * 4 + r;
        float s = 0.0f;
        #pragma unroll
        for (int k = 0; k < 8; k++) {
            float v = tile[row][lane + 32 * k];
            s = fmaf(v, v, s);
        }
        #pragma unroll
        for (int off = 16; off > 0; off >>= 1)
            s += __shfl_down_sync(0xFFFFFFFFu, s, off);
        float invn = 1.0f / fmaxf(sqrtf(__shfl_sync(0xFFFFFFFFu, s, 0)), 1e-12f);

        size_t obase = ((size_t)b * NSP + m0 + row) * KTOT;
        #pragma unroll
        for (int k = 0; k < 8; k++) {
            int c = lane + 32 * k;
            float v = tile[row][c] * invn;
            __nv_bfloat16 hi = __float2bfloat16(v);
            __nv_bfloat16 lo = __float2bfloat16(v - __bfloat162float(hi));
            dst[obase + c] = hi;
            dst[obase + 256 + c] = isP ? lo : hi;
            dst[obase + 512 + c] = isP ? hi : lo;
        }
    }
}

// ---------------------------------------------------------------------------
// Kernel 2: HMMA GEMM (128x128, K=768, 2 CTA/SM) — 3-stage ring with ONE
// barrier per K-chunk (load of c+2 issued after the barrier; WAR-safe since
// the barrier proves all warps finished mma(c-1) on stage (c-1)%3=(c+2)%3).
// exp epilogue -> g_E; accumulates row/col sums.
// ---------------------------------------------------------------------------
#define SMEM_BUFS  1024
#define STAGE_SZ   32768
#define SMEM_TOTAL (1024 + 3 * STAGE_SZ)   // 99328; 2 CTA/SM = 198KB < 228KB

__global__ __launch_bounds__(256, 2)
void gemm_exp_kernel(const float* __restrict__ alpha_p) {
    extern __shared__ char smem[];
    const uint32_t sbase = smem_u32(smem);
    float* srow = (float*)smem;
    float* scol = (float*)(smem + 512);

    const int t = threadIdx.x;
    const int w = t >> 5, lane = t & 31;
    const int b  = blockIdx.z;
    const int i0 = blockIdx.y * 128;
    const int j0 = blockIdx.x * 128;

    if (t < 128) { srow[t] = 0.0f; scol[t] = 0.0f; }

    const __nv_bfloat16* Abase = g_P + ((size_t)b * NSP + i0) * KTOT;
    const __nv_bfloat16* Bbase = g_Q + ((size_t)b * NSP + j0) * KTOT;

    auto load_chunk = [&](int c, int s) {
        uint32_t aS = sbase + SMEM_BUFS + s * STAGE_SZ;
        uint32_t bS = aS + 16384;
        #pragma unroll
        for (int u = 0; u < 4; u++) {
            int f = t + 256 * u;
            uint32_t row = f >> 3, seg = f & 7;
            uint32_t off = row * 128 + ((seg ^ (row & 7)) << 4);
            cp16(aS + off, Abase + (size_t)row * KTOT + c * 64 + seg * 8);
            cp16(bS + off, Bbase + (size_t)row * KTOT + c * 64 + seg * 8);
        }
    };

    const int wm = w >> 2, wn = w & 3;
    const int r16 = lane & 15, ahi = lane >> 4;
    const int bn  = (lane & 7) + ((lane >> 4) << 3);
    const int bkl = (lane >> 3) & 1;

    float d[4][4][4] = {};

    load_chunk(0, 0); cp_commit();
    load_chunk(1, 1); cp_commit();

    #pragma unroll 1
    for (int c = 0; c < NCHUNK; c++) {
        if (c < NCHUNK - 1) cp_wait<1>(); else cp_wait<0>();
        __syncthreads();                       // single barrier per chunk
        if (c + 2 < NCHUNK) { load_chunk(c + 2, (c + 2) % 3); cp_commit(); }

        uint32_t aS = sbase + SMEM_BUFS + (c % 3) * STAGE_SZ;
        uint32_t bS = aS + 16384;

        #pragma unroll
        for (int kk = 0; kk < 4; kk++) {
            uint32_t afr[4][4];
            #pragma unroll
            for (int mt = 0; mt < 4; mt++) {
                uint32_t row = wm * 64 + mt * 16 + r16;
                uint32_t col = (((2 * kk + ahi) ^ (r16 & 7)) << 4);
                ldmx4(afr[mt], aS + row * 128 + col);
            }
            uint32_t bfr[4][2];
            #pragma unroll
            for (int np = 0; np < 2; np++) {
                uint32_t nrow = wn * 32 + np * 16 + bn;
                uint32_t col = (((2 * kk + bkl) ^ (bn & 7)) << 4);
                uint32_t q[4];
                ldmx4(q, bS + nrow * 128 + col);
                bfr[2 * np][0] = q[0]; bfr[2 * np][1] = q[1];
                bfr[2 * np + 1][0] = q[2]; bfr[2 * np + 1][1] = q[3];
            }
            #pragma unroll
            for (int mt = 0; mt < 4; mt++)
                #pragma unroll
                for (int nt = 0; nt < 4; nt++)
                    mma16816(d[mt][nt], afr[mt], bfr[nt]);
        }
        // no trailing sync: next iteration's barrier provides WAR safety
    }

    const float alpha = __ldg(alpha_p);
    const int g = lane >> 2, tg = lane & 3;
    float csum[4][2] = {};
    float* outb = g_E + (size_t)b * BN2;

    #pragma unroll
    for (int mt = 0; mt < 4; mt++) {
        float rs0 = 0.0f, rs1 = 0.0f;
        const int row0 = i0 + wm * 64 + mt * 16 + g;
        #pragma unroll
        for (int nt = 0; nt < 4; nt++) {
            float e0 = __expf(d[mt][nt][0] * alpha);
            float e1 = __expf(d[mt][nt][1] * alpha);
            float e2 = __expf(d[mt][nt][2] * alpha);
            float e3 = __expf(d[mt][nt][3] * alpha);
            rs0 += e0 + e1; rs1 += e2 + e3;
            csum[nt][0] += e0 + e2; csum[nt][1] += e1 + e3;
            const int colg = j0 + wn * 32 + nt * 8 + tg * 2;
            *(float2*)(outb + (size_t)row0 * NSP + colg)       = make_float2(e0, e1);
            *(float2*)(outb + (size_t)(row0 + 8) * NSP + colg) = make_float2(e2, e3);
        }
        rs0 += __shfl_xor_sync(0xFFFFFFFFu, rs0, 1);
        rs0 += __shfl_xor_sync(0xFFFFFFFFu, rs0, 2);
        rs1 += __shfl_xor_sync(0xFFFFFFFFu, rs1, 1);
        rs1 += __shfl_xor_sync(0xFFFFFFFFu, rs1, 2);
        if (tg == 0) {
            atomicAdd(&srow[wm * 64 + mt * 16 + g],     rs0);
            atomicAdd(&srow[wm * 64 + mt * 16 + g + 8], rs1);
        }
    }
    #pragma unroll
    for (int nt = 0; nt < 4; nt++)
        #pragma unroll
        for (int cc = 0; cc < 2; cc++) {
            float v = csum[nt][cc];
            v += __shfl_xor_sync(0xFFFFFFFFu, v, 4);
            v += __shfl_xor_sync(0xFFFFFFFFu, v, 8);
            v += __shfl_xor_sync(0xFFFFFFFFu, v, 16);
            if (g == 0) atomicAdd(&scol[wn * 32 + nt * 8 + tg * 2 + cc], v);
        }
    __syncthreads();
    if (t < 128) {
        atomicAdd(&g_rowsum[b * NSP + i0 + t], srow[t]);
        atomicAdd(&g_colsum[b * NSP + j0 + t], scol[t]);
    }
}

// ---------------------------------------------------------------------------
// Kernel 2b: inverse sums (tiny)
// ---------------------------------------------------------------------------
__global__ void inv_kernel() {
    int i = blockIdx.x * 256 + threadIdx.x;
    g_invr[i] = 1.0f / g_rowsum[i];
    g_invc[i] = 1.0f / g_colsum[i];
}

// ---------------------------------------------------------------------------
// top-3 helpers
// ---------------------------------------------------------------------------
__device__ __forceinline__ void top3_push(float v, float& v0, float& v1, float& v2) {
    if (v > v2) {
        if (v > v1) {
            v2 = v1;
            if (v > v0) { v1 = v0; v0 = v; } else { v1 = v; }
        } else v2 = v;
    }
}
__device__ __forceinline__ void warp_reduce_top3(float& v0, float& v1, float& v2) {
    #pragma unroll
    for (int off = 16; off > 0; off >>= 1) {
        float u0 = __shfl_down_sync(0xFFFFFFFFu, v0, off);
        float u1 = __shfl_down_sync(0xFFFFFFFFu, v1, off);
        float u2 = __shfl_down_sync(0xFFFFFFFFu, v2, off);
        top3_push(u0, v0, v1, v2);
        top3_push(u1, v0, v1, v2);
        top3_push(u2, v0, v1, v2);
    }
}

// ---------------------------------------------------------------------------
// Kernel 3: finish — interleaved roles, reverse order [R16 body], with reg
// cap for occupancy (min 7 CTAs/SM).
// ---------------------------------------------------------------------------
__global__ __launch_bounds__(256, 7)
void finish_kernel(float* __restrict__ xcq, float* __restrict__ xcp,
                   float* __restrict__ valp) {
    __shared__ float tile[2][64][33];     // 17.4 KB
    const int b  = (BATCH - 1) - blockIdx.y;   // reverse batch order
    const int bx = blockIdx.x;
    const int t  = threadIdx.x;
    const int w  = t >> 5, lane = t & 31;

    if (bx % 3 == 0) {
        // ---------------- row role (reverse row order) ----------------
        const int ri = 511 - bx / 3;
        const int i  = ri * 8 + w;
        const float invr = g_invr[b * NSP + i];
        const float* invc = g_invc + b * NSP;
        const float* src = g_E + (size_t)b * BN2 + (size_t)i * NSP;
        float*       dst = xcq + (size_t)b * BN2 + (size_t)i * NSP;

        float v0 = -1e30f, v1 = -1e30f, v2 = -1e30f;
        for (int jb = lane * 4; jb < NSP; jb += 128) {
            float4 e  = *(const float4*)(src + jb);
            float4 ic = *(const float4*)(invc + jb);
            float x0 = e.x * e.x * invr * ic.x;
            float x1 = e.y * e.y * invr * ic.y;
            float x2 = e.z * e.z * invr * ic.z;
            float x3 = e.w * e.w * invr * ic.w;
            *(float4*)(dst + jb) = make_float4(x0, x1, x2, x3);
            top3_push(x0, v0, v1, v2);
            top3_push(x1, v0, v1, v2);
            top3_push(x2, v0, v1, v2);
            top3_push(x3, v0, v1, v2);
        }
        warp_reduce_top3(v0, v1, v2);
        if (lane == 0) {
            valp[b * 3 * NSP + 0 * NSP + i] = v0;
            valp[b * 3 * NSP + 1 * NSP + i] = v1;
            valp[b * 3 * NSP + 2 * NSP + i] = v2;
        }
    } else {
        // ------------- col role: 32-col strip x 512-row octant -------------
        const int ci  = bx - 1 - bx / 3;          // 0..1023
        const int j0  = (ci & 127) * 32;
        const int oct = 7 - (ci >> 7);            // reverse octant order
        const int i0  = oct * 512;
        const int lr  = t >> 3;                   // 0..31
        const int lc4 = (t & 7) * 4;              // 0,4,...,28
        const float4 ic4 = *(const float4*)(g_invc + b * NSP + j0 + lc4);
        const float* invr = g_invr + b * NSP;
        const float* src = g_E + (size_t)b * BN2;
        float*       dst = xcp + (size_t)b * BN2;

        float c0[4], c1[4], c2[4];
        #pragma unroll
        for (int k = 0; k < 4; k++) { c0[k] = -1e30f; c1[k] = -1e30f; c2[k] = -1e30f; }

        auto load = [&](int ic, int bf) {
            #pragma unroll
            for (int u = 0; u < 2; u++) {
                const int r = lr + u * 32;
                float4 e = *(const float4*)(src + (size_t)(ic + r) * NSP + j0 + lc4);
                const float ir = invr[ic + r];
                float* tp = &tile[bf][r][lc4];
                tp[0] = e.x * e.x * ir * ic4.x;
                tp[1] = e.y * e.y * ir * ic4.y;
                tp[2] = e.z * e.z * ir * ic4.z;
                tp[3] = e.w * e.w * ir * ic4.w;
            }
        };

        load(i0 + 512 - 64, 0);
        int bf = 0;

        #pragma unroll 1
        for (int ic = i0 + 512 - 64; ic >= i0; ic -= 64) {
            __syncthreads();
            if (ic - 64 >= i0) load(ic - 64, bf ^ 1);

            #pragma unroll
            for (int cc = 0; cc < 4; cc++) {
                const int col = w * 4 + cc;
                #pragma unroll
                for (int g2 = 0; g2 < 2; g2++) {
                    float v = tile[bf][g2 * 32 + lane][col];
                    dst[(size_t)(j0 + col) * NSP + ic + g2 * 32 + lane] = v;
                    top3_push(v, c0[cc], c1[cc], c2[cc]);
                }
            }
            bf ^= 1;
        }

        #pragma unroll
        for (int cc = 0; cc < 4; cc++) {
            float v0 = c0[cc], v1 = c1[cc], v2 = c2[cc];
            warp_reduce_top3(v0, v1, v2);
            if (lane == 0) {
                const int base = (b * 8 + oct) * 3;
                const int j = j0 + w * 4 + cc;
                g_cpart[(base + 0) * NSP + j] = v0;
                g_cpart[(base + 1) * NSP + j] = v1;
                g_cpart[(base + 2) * NSP + j] = v2;
            }
        }
    }
}

// ---------------------------------------------------------------------------
// Kernel 4: merge 8 column partials -> valq
// ---------------------------------------------------------------------------
__global__ __launch_bounds__(256)
void valq_reduce_kernel(float* __restrict__ valq) {
    const int b = blockIdx.y;
    const int j = blockIdx.x * 256 + threadIdx.x;
    float v0 = -1e30f, v1 = -1e30f, v2 = -1e30f;
    #pragma unroll
    for (int p = 0; p < 8; p++) {
        const int base = (b * 8 + p) * 3;
        top3_push(g_cpart[(base + 0) * NSP + j], v0, v1, v2);
        top3_push(g_cpart[(base + 1) * NSP + j], v0, v1, v2);
        top3_push(g_cpart[(base + 2) * NSP + j], v0, v1, v2);
    }
    valq[b * 3 * NSP + 0 * NSP + j] = v0;
    valq[b * 3 * NSP + 1 * NSP + j] = v1;
    valq[b * 3 * NSP + 2 * NSP + j] = v2;
}

// ---------------------------------------------------------------------------
extern "C" void kernel_launch(void* const* d_in, const int* in_sizes, int n_in,
                              void* d_out, int out_size) {
    const float* xp    = (const float*)d_in[0];
    const float* xq    = (const float*)d_in[1];
    const float* alpha = (const float*)d_in[2];

    float* valp = (float*)d_out;
    float* valq = valp + BATCH * 3 * NSP;
    float* xcp  = valq + BATCH * 3 * NSP;
    float* xcq  = xcp + (size_t)BATCH * BN2;

    cudaFuncSetAttribute(gemm_exp_kernel,
                         cudaFuncAttributeMaxDynamicSharedMemorySize, SMEM_TOTAL);

    prep_kernel<<<dim3(128, BATCH, 2), 256>>>(xp, xq);
    gemm_exp_kernel<<<dim3(32, 32, BATCH), 256, SMEM_TOTAL>>>(alpha);
    inv_kernel<<<64, 256>>>();
    finish_kernel<<<dim3(1536, BATCH), 256>>>(xcq, xcp, valp);
    valq_reduce_kernel<<<dim3(16, BATCH), 256>>>(valq);
}